// round 1
// baseline (speedup 1.0000x reference)
#include <cuda_runtime.h>
#include <cuda_bf16.h>
#include <math.h>

// Problem constants (from reference setup_inputs)
#define T_FR 32
#define NN 512
#define FF 256
#define HH 8
#define LL 3
#define DIN 3
#define NEG_BIG (-9e15f)

// ---------------- scratch (device globals; allocation-free rule) ----------------
__device__ float g_x[T_FR * NN * FF];                 // 16 MB current features
__device__ float g_Wh[T_FR * HH * NN * FF];           // 128 MB per-head Wh (reused for out-head)
__device__ float g_xcat[T_FR * NN * HH * FF];         // 128 MB concatenated heads
__device__ float g_f[T_FR * HH * NN];                 // source terms
__device__ float g_g[T_FR * HH * NN];                 // target terms
__device__ float g_P[(long)T_FR * HH * NN * NN];      // 256 MB attention probs

// ---------------- input projection: x = pose @ Wp + bp ----------------
__global__ void input_proj_kernel(const float* __restrict__ pose,
                                  const float* __restrict__ Wp,
                                  const float* __restrict__ bp,
                                  float* __restrict__ x) {
    long idx = (long)blockIdx.x * blockDim.x + threadIdx.x;
    if (idx >= (long)T_FR * NN * FF) return;
    int f = (int)(idx % FF);
    long tn = idx / FF;
    const float* p = pose + tn * DIN;
    x[idx] = p[0] * Wp[f] + p[1] * Wp[FF + f] + p[2] * Wp[2 * FF + f] + bp[f];
}

// ---------------- generic batched tiled GEMM (fp32), C = A@B, optional ELU epilogue ----------------
// A offset = (b/aDiv)*aStride ; B offset = (b%bMod)*bStride
// C offset = (b/cDiv)*cOuter + (b%cDiv)*cInner
// epi: 0 = none, 1 = elu, 2 = elu(elu)
__global__ __launch_bounds__(256)
void gemm_batched(const float* __restrict__ A, const float* __restrict__ B,
                  float* __restrict__ C,
                  int K, int lda, int ldb, int ldc,
                  long aStride, int aDiv, long bStride, int bMod,
                  long cOuter, int cDiv, long cInner, int epi) {
    int b = blockIdx.z;
    const float* Ab = A + (long)(b / aDiv) * aStride;
    const float* Bb = B + (long)(b % bMod) * bStride;
    float* Cb = C + (long)(b / cDiv) * cOuter + (long)(b % cDiv) * cInner;

    __shared__ float As[64][17];
    __shared__ float Bs[16][68];

    int tid = threadIdx.x;
    int tx = tid & 15;          // 0..15  -> 4 cols each
    int ty = tid >> 4;          // 0..15  -> 4 rows each
    int row0 = blockIdx.y * 64;
    int col0 = blockIdx.x * 64;

    int am = tid >> 2;                 // 0..63 A-tile row
    int ak = (tid & 3) << 2;           // 0,4,8,12
    int bk = tid >> 4;                 // 0..15 B-tile k
    int bn = (tid & 15) << 2;          // 0..60

    const float* aptr = Ab + (long)(row0 + am) * lda + ak;
    const float* bptr = Bb + (long)bk * ldb + col0 + bn;

    float acc[4][4] = {};

    for (int k0 = 0; k0 < K; k0 += 16) {
        float4 av = *(const float4*)(aptr + k0);
        float4 bv = *(const float4*)(bptr + (long)k0 * ldb);
        As[am][ak + 0] = av.x; As[am][ak + 1] = av.y;
        As[am][ak + 2] = av.z; As[am][ak + 3] = av.w;
        *(float4*)&Bs[bk][bn] = bv;
        __syncthreads();

        #pragma unroll
        for (int k = 0; k < 16; k++) {
            float ar0 = As[ty * 4 + 0][k];
            float ar1 = As[ty * 4 + 1][k];
            float ar2 = As[ty * 4 + 2][k];
            float ar3 = As[ty * 4 + 3][k];
            float4 br = *(const float4*)&Bs[k][tx * 4];
            acc[0][0] += ar0 * br.x; acc[0][1] += ar0 * br.y;
            acc[0][2] += ar0 * br.z; acc[0][3] += ar0 * br.w;
            acc[1][0] += ar1 * br.x; acc[1][1] += ar1 * br.y;
            acc[1][2] += ar1 * br.z; acc[1][3] += ar1 * br.w;
            acc[2][0] += ar2 * br.x; acc[2][1] += ar2 * br.y;
            acc[2][2] += ar2 * br.z; acc[2][3] += ar2 * br.w;
            acc[3][0] += ar3 * br.x; acc[3][1] += ar3 * br.y;
            acc[3][2] += ar3 * br.z; acc[3][3] += ar3 * br.w;
        }
        __syncthreads();
    }

    #pragma unroll
    for (int i = 0; i < 4; i++) {
        float* cp = Cb + (long)(row0 + ty * 4 + i) * ldc + col0 + tx * 4;
        float4 v;
        float r[4] = {acc[i][0], acc[i][1], acc[i][2], acc[i][3]};
        #pragma unroll
        for (int j = 0; j < 4; j++) {
            float u = r[j];
            if (epi >= 1) u = (u >= 0.f) ? u : expm1f(u);
            if (epi == 2) u = (u >= 0.f) ? u : expm1f(u);
            r[j] = u;
        }
        v.x = r[0]; v.y = r[1]; v.z = r[2]; v.w = r[3];
        *(float4*)cp = v;
    }
}

// ---------------- f/g terms: f = Wh @ a[:F], g = Wh @ a[F:] (one warp per row) ----------------
__global__ void fg_kernel(const float* __restrict__ Wh, const float* __restrict__ a,
                          int aMod, float* __restrict__ f, float* __restrict__ g,
                          int batches) {
    long w = ((long)blockIdx.x * blockDim.x + threadIdx.x) >> 5;
    int lane = threadIdx.x & 31;
    if (w >= (long)batches * NN) return;
    int b = (int)(w / NN);
    const float* row = Wh + w * FF;
    const float* ar = a + (long)(b % aMod) * (2 * FF);
    float s1 = 0.f, s2 = 0.f;
    #pragma unroll
    for (int i = 0; i < FF / 32; i++) {
        float v = row[lane + 32 * i];
        s1 += v * ar[lane + 32 * i];
        s2 += v * ar[FF + lane + 32 * i];
    }
    #pragma unroll
    for (int o = 16; o > 0; o >>= 1) {
        s1 += __shfl_down_sync(0xffffffffu, s1, o);
        s2 += __shfl_down_sync(0xffffffffu, s2, o);
    }
    if (lane == 0) { f[w] = s1; g[w] = s2; }
}

// ---------------- masked leakyrelu logits + row softmax -> P ----------------
__global__ void softmax_kernel(const float* __restrict__ f, const float* __restrict__ g,
                               const int* __restrict__ adj, float* __restrict__ P) {
    long r = blockIdx.x;            // r = b*NN + i
    int b = (int)(r / NN);
    int i = (int)(r % NN);
    int tid = threadIdx.x;          // 256 threads, 2 cols each
    __shared__ float red[256];

    float fi = f[r];
    const float* gb = g + (long)b * NN;
    const int* arow = adj + (long)i * NN;

    float x0 = fi + gb[tid];
    x0 = (x0 >= 0.f) ? x0 : 0.2f * x0;
    float v0 = arow[tid] ? x0 : NEG_BIG;
    float x1 = fi + gb[tid + 256];
    x1 = (x1 >= 0.f) ? x1 : 0.2f * x1;
    float v1 = arow[tid + 256] ? x1 : NEG_BIG;

    red[tid] = fmaxf(v0, v1);
    __syncthreads();
    #pragma unroll
    for (int s = 128; s > 0; s >>= 1) {
        if (tid < s) red[tid] = fmaxf(red[tid], red[tid + s]);
        __syncthreads();
    }
    float mx = red[0];
    __syncthreads();

    float e0 = (v0 < -1e30f) ? 0.f : __expf(v0 - mx);
    float e1 = (v1 < -1e30f) ? 0.f : __expf(v1 - mx);
    red[tid] = e0 + e1;
    __syncthreads();
    #pragma unroll
    for (int s = 128; s > 0; s >>= 1) {
        if (tid < s) red[tid] += red[tid + s];
        __syncthreads();
    }
    float inv = 1.0f / red[0];

    float* prow = P + r * NN;
    prow[tid] = e0 * inv;
    prow[tid + 256] = e1 * inv;
}

// ---------------- final pool: out[t] = mean_n(x[t]) @ Wo + bo ----------------
__global__ void pool_kernel(const float* __restrict__ x, const float* __restrict__ Wo,
                            const float* __restrict__ bo, float* __restrict__ out) {
    int t = blockIdx.x;
    int f = threadIdx.x;          // 256
    __shared__ float m[FF];
    const float* xt = x + (long)t * NN * FF;
    float s = 0.f;
    for (int n = 0; n < NN; n++) s += xt[n * FF + f];
    m[f] = s * (1.0f / NN);
    __syncthreads();
    float o = bo[f];
    for (int k = 0; k < FF; k++) o += m[k] * Wo[k * FF + f];
    out[t * FF + f] = o;
}

// ---------------- host orchestration ----------------
extern "C" void kernel_launch(void* const* d_in, const int* in_sizes, int n_in,
                              void* d_out, int out_size) {
    const float* pose    = (const float*)d_in[0];   // [32,512,3]
    const int*   adj     = (const int*)  d_in[1];   // [512,512]
    const float* Wp      = (const float*)d_in[2];   // [3,256]
    const float* bp      = (const float*)d_in[3];   // [256]
    const float* W_heads = (const float*)d_in[4];   // [3,8,256,256]
    const float* a_heads = (const float*)d_in[5];   // [3,8,512]
    const float* W_out   = (const float*)d_in[6];   // [3,2048,256]
    const float* a_out   = (const float*)d_in[7];   // [3,512]
    const float* Wo      = (const float*)d_in[8];   // [256,256]
    const float* bo      = (const float*)d_in[9];   // [256]
    float* out = (float*)d_out;

    float *x, *Wh, *xcat, *fb, *gb, *P;
    cudaGetSymbolAddress((void**)&x,    g_x);
    cudaGetSymbolAddress((void**)&Wh,   g_Wh);
    cudaGetSymbolAddress((void**)&xcat, g_xcat);
    cudaGetSymbolAddress((void**)&fb,   g_f);
    cudaGetSymbolAddress((void**)&gb,   g_g);
    cudaGetSymbolAddress((void**)&P,    g_P);

    // 1. input projection
    {
        long total = (long)T_FR * NN * FF;
        input_proj_kernel<<<(unsigned)((total + 255) / 256), 256>>>(pose, Wp, bp, x);
    }

    for (int l = 0; l < LL; l++) {
        const float* Wl = W_heads + (long)l * HH * FF * FF;
        const float* al = a_heads + (long)l * HH * 2 * FF;
        const float* Wol = W_out + (long)l * (HH * FF) * FF;
        const float* aol = a_out + (long)l * 2 * FF;

        // 2a. Wh[t,h] = x[t] @ W_heads[l,h]   (batch = T*H, M=512, N=256, K=256)
        {
            dim3 grid(FF / 64, NN / 64, T_FR * HH);
            gemm_batched<<<grid, 256>>>(x, Wl, Wh,
                FF, FF, FF, FF,
                (long)NN * FF, HH,           // A: per-frame
                (long)FF * FF, HH,           // B: per-head
                (long)NN * FF, 1, 0,         // C: contiguous batches
                0);
        }
        // 2b. f,g per head
        {
            long warps = (long)T_FR * HH * NN;
            fg_kernel<<<(unsigned)((warps * 32 + 255) / 256), 256>>>(Wh, al, HH, fb, gb, T_FR * HH);
        }
        // 2c. softmax -> P
        softmax_kernel<<<T_FR * HH * NN, 256>>>(fb, gb, adj, P);
        // 2d. head out: xcat[t][:, h*256:(h+1)*256] = elu(P[t,h] @ Wh[t,h])
        {
            dim3 grid(FF / 64, NN / 64, T_FR * HH);
            gemm_batched<<<grid, 256>>>(P, Wh, xcat,
                NN, NN, FF, HH * FF,
                (long)NN * NN, 1,            // A: P per batch
                (long)NN * FF, T_FR * HH,    // B: Wh per batch
                (long)NN * HH * FF, HH, FF,  // C: interleave heads
                1);
        }
        // 2e. Whout[t] = xcat[t] @ W_out[l]   (batch = T, K = 2048)
        {
            dim3 grid(FF / 64, NN / 64, T_FR);
            gemm_batched<<<grid, 256>>>(xcat, Wol, Wh,
                HH * FF, HH * FF, FF, FF,
                (long)NN * HH * FF, 1,
                0, 1,                        // B shared across batch
                (long)NN * FF, 1, 0,
                0);
        }
        // 2f. f,g for out-head
        {
            long warps = (long)T_FR * NN;
            fg_kernel<<<(unsigned)((warps * 32 + 255) / 256), 256>>>(Wh, aol, 1, fb, gb, T_FR);
        }
        // 2g. softmax -> P
        softmax_kernel<<<T_FR * NN, 256>>>(fb, gb, adj, P);
        // 2h. x[t] = elu(elu(P[t] @ Whout[t]))
        {
            dim3 grid(FF / 64, NN / 64, T_FR);
            gemm_batched<<<grid, 256>>>(P, Wh, x,
                NN, NN, FF, FF,
                (long)NN * NN, 1,
                (long)NN * FF, T_FR,
                (long)NN * FF, 1, 0,
                2);
        }
    }

    // 3. pool + output projection
    pool_kernel<<<T_FR, 256>>>(x, Wo, bo, out);
}

// round 2
// speedup vs baseline: 1.2792x; 1.2792x over previous
#include <cuda_runtime.h>
#include <cuda_bf16.h>
#include <math.h>

// Problem constants
#define T_FR 32
#define NN 512
#define FF 256
#define HH 8
#define LL 3
#define DIN 3
#define NEG_BIG (-9e15f)

#define BM 128
#define BN 64
#define BK 32

// ---------------- scratch (device globals; allocation-free rule) ----------------
__device__ float g_x[T_FR * NN * FF];
__device__ float g_Wh[T_FR * HH * NN * FF];
__device__ float g_xcat[T_FR * NN * HH * FF];
__device__ float g_f[T_FR * HH * NN];
__device__ float g_g[T_FR * HH * NN];
__device__ float g_P[(long)T_FR * HH * NN * NN];
__device__ unsigned g_adjmask[NN * (NN / 32)];

// ---------------- helpers ----------------
__device__ __forceinline__ void split_bf16(float x, unsigned short& h, unsigned short& l) {
    __nv_bfloat16 bh = __float2bfloat16(x);
    float r = x - __bfloat162float(bh);
    __nv_bfloat16 bl = __float2bfloat16(r);
    h = __bfloat16_as_ushort(bh);
    l = __bfloat16_as_ushort(bl);
}

__device__ __forceinline__ void mma16816(float* c, const unsigned* a, const unsigned* b) {
    asm volatile(
        "mma.sync.aligned.m16n8k16.row.col.f32.bf16.bf16.f32 "
        "{%0,%1,%2,%3}, {%4,%5,%6,%7}, {%8,%9}, {%0,%1,%2,%3};\n"
        : "+f"(c[0]), "+f"(c[1]), "+f"(c[2]), "+f"(c[3])
        : "r"(a[0]), "r"(a[1]), "r"(a[2]), "r"(a[3]), "r"(b[0]), "r"(b[1]));
}

// ---------------- input projection ----------------
__global__ void input_proj_kernel(const float* __restrict__ pose,
                                  const float* __restrict__ Wp,
                                  const float* __restrict__ bp,
                                  float* __restrict__ x) {
    long idx = (long)blockIdx.x * blockDim.x + threadIdx.x;
    if (idx >= (long)T_FR * NN * FF) return;
    int f = (int)(idx % FF);
    long tn = idx / FF;
    const float* p = pose + tn * DIN;
    x[idx] = p[0] * Wp[f] + p[1] * Wp[FF + f] + p[2] * Wp[2 * FF + f] + bp[f];
}

// ---------------- adjacency bitmask ----------------
__global__ void adjmask_kernel(const int* __restrict__ adj, unsigned* __restrict__ m) {
    int i = blockIdx.x;
    int w = threadIdx.x;                 // 0..15
    const int* row = adj + (long)i * NN + w * 32;
    unsigned bits = 0;
    #pragma unroll
    for (int b = 0; b < 32; b++) bits |= (row[b] > 0 ? 1u : 0u) << b;
    m[i * 16 + w] = bits;
}

// ---------------- bf16 split-3 tensor-core batched GEMM, C = A@B (+ optional ELU) ----------------
// A offset = (b/aDiv)*aStride ; B offset = (b%bMod)*bStride
// C offset = (b/cDiv)*cOuter + (b%cDiv)*cInner
// epi: 0 = none, 1 = elu, 2 = elu(elu)
__global__ __launch_bounds__(256, 2)
void gemm_mma(const float* __restrict__ A, const float* __restrict__ B,
              float* __restrict__ C,
              int K, int lda, int ldb, int ldc,
              long aStride, int aDiv, long bStride, int bMod,
              long cOuter, int cDiv, long cInner, int epi) {
    int b = blockIdx.z;
    const float* Ab = A + (long)(b / aDiv) * aStride;
    const float* Bb = B + (long)(b % bMod) * bStride;
    float* Cb = C + (long)(b / cDiv) * cOuter + (long)(b % cDiv) * cInner;

    __shared__ __align__(16) unsigned short Ahi[BM][40];
    __shared__ __align__(16) unsigned short Alo[BM][40];
    __shared__ __align__(16) unsigned short Bhi[BN][40];
    __shared__ __align__(16) unsigned short Blo[BN][40];

    int tid = threadIdx.x;
    int lane = tid & 31;
    int warp = tid >> 5;
    int wm = warp & 3;      // m quadrant (0..3), rows wm*32
    int wn = warp >> 2;     // n half (0..1), cols wn*32
    int row0 = blockIdx.y * BM;
    int col0 = blockIdx.x * BN;

    int arow = tid >> 1;            // 0..127
    int acol = (tid & 1) << 4;      // 0 or 16

    int g = lane >> 2;              // 0..7
    int q = lane & 3;               // 0..3

    float acc[2][4][4];
    #pragma unroll
    for (int i = 0; i < 2; i++)
        #pragma unroll
        for (int j = 0; j < 4; j++)
            #pragma unroll
            for (int k = 0; k < 4; k++) acc[i][j][k] = 0.f;

    for (int k0 = 0; k0 < K; k0 += BK) {
        // --- load A tile [BM x BK], split to bf16 hi/lo ---
        {
            const float* ap = Ab + (long)(row0 + arow) * lda + k0 + acol;
            #pragma unroll
            for (int i = 0; i < 4; i++) {
                float4 v = *(const float4*)(ap + i * 4);
                unsigned short h0, h1, h2, h3, l0, l1, l2, l3;
                split_bf16(v.x, h0, l0); split_bf16(v.y, h1, l1);
                split_bf16(v.z, h2, l2); split_bf16(v.w, h3, l3);
                int c = acol + i * 4;
                *(unsigned*)&Ahi[arow][c]     = (unsigned)h0 | ((unsigned)h1 << 16);
                *(unsigned*)&Ahi[arow][c + 2] = (unsigned)h2 | ((unsigned)h3 << 16);
                *(unsigned*)&Alo[arow][c]     = (unsigned)l0 | ((unsigned)l1 << 16);
                *(unsigned*)&Alo[arow][c + 2] = (unsigned)l2 | ((unsigned)l3 << 16);
            }
        }
        // --- load B tile [BK x BN], transpose to smem [n][k], split hi/lo ---
        #pragma unroll
        for (int i = 0; i < 2; i++) {
            int idx4 = tid * 2 + i;
            int krow = idx4 >> 4;           // 0..31
            int ncol = (idx4 & 15) << 2;    // 0..60
            float4 v = *(const float4*)(Bb + (long)(k0 + krow) * ldb + col0 + ncol);
            unsigned short h, l;
            split_bf16(v.x, h, l); Bhi[ncol + 0][krow] = h; Blo[ncol + 0][krow] = l;
            split_bf16(v.y, h, l); Bhi[ncol + 1][krow] = h; Blo[ncol + 1][krow] = l;
            split_bf16(v.z, h, l); Bhi[ncol + 2][krow] = h; Blo[ncol + 2][krow] = l;
            split_bf16(v.w, h, l); Bhi[ncol + 3][krow] = h; Blo[ncol + 3][krow] = l;
        }
        __syncthreads();

        #pragma unroll
        for (int kk = 0; kk < BK; kk += 16) {
            unsigned ah[2][4], al[2][4], bh[4][2], bl[4][2];
            #pragma unroll
            for (int mt = 0; mt < 2; mt++) {
                int r = wm * 32 + mt * 16 + g;
                ah[mt][0] = *(const unsigned*)&Ahi[r][kk + 2 * q];
                ah[mt][1] = *(const unsigned*)&Ahi[r + 8][kk + 2 * q];
                ah[mt][2] = *(const unsigned*)&Ahi[r][kk + 8 + 2 * q];
                ah[mt][3] = *(const unsigned*)&Ahi[r + 8][kk + 8 + 2 * q];
                al[mt][0] = *(const unsigned*)&Alo[r][kk + 2 * q];
                al[mt][1] = *(const unsigned*)&Alo[r + 8][kk + 2 * q];
                al[mt][2] = *(const unsigned*)&Alo[r][kk + 8 + 2 * q];
                al[mt][3] = *(const unsigned*)&Alo[r + 8][kk + 8 + 2 * q];
            }
            #pragma unroll
            for (int nt = 0; nt < 4; nt++) {
                int n = wn * 32 + nt * 8 + g;
                bh[nt][0] = *(const unsigned*)&Bhi[n][kk + 2 * q];
                bh[nt][1] = *(const unsigned*)&Bhi[n][kk + 8 + 2 * q];
                bl[nt][0] = *(const unsigned*)&Blo[n][kk + 2 * q];
                bl[nt][1] = *(const unsigned*)&Blo[n][kk + 8 + 2 * q];
            }
            // three split-product passes; 8 independent acc tiles each for ILP
            #pragma unroll
            for (int mt = 0; mt < 2; mt++)
                #pragma unroll
                for (int nt = 0; nt < 4; nt++) mma16816(acc[mt][nt], ah[mt], bh[nt]);
            #pragma unroll
            for (int mt = 0; mt < 2; mt++)
                #pragma unroll
                for (int nt = 0; nt < 4; nt++) mma16816(acc[mt][nt], al[mt], bh[nt]);
            #pragma unroll
            for (int mt = 0; mt < 2; mt++)
                #pragma unroll
                for (int nt = 0; nt < 4; nt++) mma16816(acc[mt][nt], ah[mt], bl[nt]);
        }
        __syncthreads();
    }

    // --- epilogue ---
    #pragma unroll
    for (int mt = 0; mt < 2; mt++) {
        #pragma unroll
        for (int nt = 0; nt < 4; nt++) {
            int r = row0 + wm * 32 + mt * 16 + g;
            int c = col0 + wn * 32 + nt * 8 + 2 * q;
            float vv[4] = {acc[mt][nt][0], acc[mt][nt][1], acc[mt][nt][2], acc[mt][nt][3]};
            #pragma unroll
            for (int j = 0; j < 4; j++) {
                float u = vv[j];
                if (epi >= 1) u = (u >= 0.f) ? u : expm1f(u);
                if (epi == 2) u = (u >= 0.f) ? u : expm1f(u);
                vv[j] = u;
            }
            *(float2*)&Cb[(long)r * ldc + c] = make_float2(vv[0], vv[1]);
            *(float2*)&Cb[(long)(r + 8) * ldc + c] = make_float2(vv[2], vv[3]);
        }
    }
}

// ---------------- f/g terms (one warp per row) ----------------
__global__ void fg_kernel(const float* __restrict__ Wh, const float* __restrict__ a,
                          int aMod, float* __restrict__ f, float* __restrict__ g,
                          int batches) {
    long w = ((long)blockIdx.x * blockDim.x + threadIdx.x) >> 5;
    int lane = threadIdx.x & 31;
    if (w >= (long)batches * NN) return;
    int b = (int)(w / NN);
    const float* row = Wh + w * FF;
    const float* ar = a + (long)(b % aMod) * (2 * FF);
    float s1 = 0.f, s2 = 0.f;
    #pragma unroll
    for (int i = 0; i < FF / 32; i++) {
        float v = row[lane + 32 * i];
        s1 += v * ar[lane + 32 * i];
        s2 += v * ar[FF + lane + 32 * i];
    }
    #pragma unroll
    for (int o = 16; o > 0; o >>= 1) {
        s1 += __shfl_down_sync(0xffffffffu, s1, o);
        s2 += __shfl_down_sync(0xffffffffu, s2, o);
    }
    if (lane == 0) { f[w] = s1; g[w] = s2; }
}

// ---------------- masked leakyrelu + row softmax (bitmask adjacency) ----------------
__global__ void softmax_kernel(const float* __restrict__ f, const float* __restrict__ g,
                               const unsigned* __restrict__ adjm, float* __restrict__ P) {
    long r = blockIdx.x;            // r = b*NN + i
    int b = (int)(r / NN);
    int i = (int)(r % NN);
    int tid = threadIdx.x;          // 256 threads, 2 cols each
    __shared__ float red[256];

    float fi = f[r];
    const float* gb = g + (long)b * NN;
    const unsigned* mrow = adjm + i * 16;

    int j0 = tid, j1 = tid + 256;
    bool m0 = (mrow[j0 >> 5] >> (j0 & 31)) & 1u;
    bool m1 = (mrow[j1 >> 5] >> (j1 & 31)) & 1u;

    float x0 = fi + gb[j0];
    x0 = (x0 >= 0.f) ? x0 : 0.2f * x0;
    float v0 = m0 ? x0 : NEG_BIG;
    float x1 = fi + gb[j1];
    x1 = (x1 >= 0.f) ? x1 : 0.2f * x1;
    float v1 = m1 ? x1 : NEG_BIG;

    red[tid] = fmaxf(v0, v1);
    __syncthreads();
    #pragma unroll
    for (int s = 128; s > 0; s >>= 1) {
        if (tid < s) red[tid] = fmaxf(red[tid], red[tid + s]);
        __syncthreads();
    }
    float mx = red[0];
    __syncthreads();

    float e0 = m0 ? __expf(v0 - mx) : 0.f;
    float e1 = m1 ? __expf(v1 - mx) : 0.f;
    red[tid] = e0 + e1;
    __syncthreads();
    #pragma unroll
    for (int s = 128; s > 0; s >>= 1) {
        if (tid < s) red[tid] += red[tid + s];
        __syncthreads();
    }
    float inv = 1.0f / red[0];

    float* prow = P + r * NN;
    prow[j0] = e0 * inv;
    prow[j1] = e1 * inv;
}

// ---------------- final pool ----------------
__global__ void pool_kernel(const float* __restrict__ x, const float* __restrict__ Wo,
                            const float* __restrict__ bo, float* __restrict__ out) {
    int t = blockIdx.x;
    int f = threadIdx.x;
    __shared__ float m[FF];
    const float* xt = x + (long)t * NN * FF;
    float s = 0.f;
    for (int n = 0; n < NN; n++) s += xt[n * FF + f];
    m[f] = s * (1.0f / NN);
    __syncthreads();
    float o = bo[f];
    for (int k = 0; k < FF; k++) o += m[k] * Wo[k * FF + f];
    out[t * FF + f] = o;
}

// ---------------- host orchestration ----------------
extern "C" void kernel_launch(void* const* d_in, const int* in_sizes, int n_in,
                              void* d_out, int out_size) {
    const float* pose    = (const float*)d_in[0];
    const int*   adj     = (const int*)  d_in[1];
    const float* Wp      = (const float*)d_in[2];
    const float* bp      = (const float*)d_in[3];
    const float* W_heads = (const float*)d_in[4];
    const float* a_heads = (const float*)d_in[5];
    const float* W_out   = (const float*)d_in[6];
    const float* a_out   = (const float*)d_in[7];
    const float* Wo      = (const float*)d_in[8];
    const float* bo      = (const float*)d_in[9];
    float* out = (float*)d_out;

    float *x, *Wh, *xcat, *fb, *gb, *P;
    unsigned* adjm;
    cudaGetSymbolAddress((void**)&x,    g_x);
    cudaGetSymbolAddress((void**)&Wh,   g_Wh);
    cudaGetSymbolAddress((void**)&xcat, g_xcat);
    cudaGetSymbolAddress((void**)&fb,   g_f);
    cudaGetSymbolAddress((void**)&gb,   g_g);
    cudaGetSymbolAddress((void**)&P,    g_P);
    cudaGetSymbolAddress((void**)&adjm, g_adjmask);

    adjmask_kernel<<<NN, 16>>>(adj, adjm);

    {
        long total = (long)T_FR * NN * FF;
        input_proj_kernel<<<(unsigned)((total + 255) / 256), 256>>>(pose, Wp, bp, x);
    }

    for (int l = 0; l < LL; l++) {
        const float* Wl  = W_heads + (long)l * HH * FF * FF;
        const float* al  = a_heads + (long)l * HH * 2 * FF;
        const float* Wol = W_out   + (long)l * (HH * FF) * FF;
        const float* aol = a_out   + (long)l * 2 * FF;

        // 2a. Wh[t,h] = x[t] @ W_heads[l,h]
        {
            dim3 grid(FF / BN, NN / BM, T_FR * HH);
            gemm_mma<<<grid, 256>>>(x, Wl, Wh,
                FF, FF, FF, FF,
                (long)NN * FF, HH,
                (long)FF * FF, HH,
                (long)NN * FF, 1, 0,
                0);
        }
        // 2b. f,g per head
        {
            long warps = (long)T_FR * HH * NN;
            fg_kernel<<<(unsigned)((warps * 32 + 255) / 256), 256>>>(Wh, al, HH, fb, gb, T_FR * HH);
        }
        // 2c. softmax -> P
        softmax_kernel<<<T_FR * HH * NN, 256>>>(fb, gb, adjm, P);
        // 2d. xcat[t][:, h*F:(h+1)*F] = elu(P[t,h] @ Wh[t,h])
        {
            dim3 grid(FF / BN, NN / BM, T_FR * HH);
            gemm_mma<<<grid, 256>>>(P, Wh, xcat,
                NN, NN, FF, HH * FF,
                (long)NN * NN, 1,
                (long)NN * FF, T_FR * HH,
                (long)NN * HH * FF, HH, FF,
                1);
        }
        // 2e. Whout[t] = xcat[t] @ W_out[l]
        {
            dim3 grid(FF / BN, NN / BM, T_FR);
            gemm_mma<<<grid, 256>>>(xcat, Wol, Wh,
                HH * FF, HH * FF, FF, FF,
                (long)NN * HH * FF, 1,
                0, 1,
                (long)NN * FF, 1, 0,
                0);
        }
        // 2f. f,g for out-head
        {
            long warps = (long)T_FR * NN;
            fg_kernel<<<(unsigned)((warps * 32 + 255) / 256), 256>>>(Wh, aol, 1, fb, gb, T_FR);
        }
        // 2g. softmax -> P
        softmax_kernel<<<T_FR * NN, 256>>>(fb, gb, adjm, P);
        // 2h. x[t] = elu(elu(P[t] @ Whout[t]))
        {
            dim3 grid(FF / BN, NN / BM, T_FR);
            gemm_mma<<<grid, 256>>>(P, Wh, x,
                NN, NN, FF, FF,
                (long)NN * NN, 1,
                (long)NN * FF, T_FR,
                (long)NN * FF, 1, 0,
                2);
        }
    }

    pool_kernel<<<T_FR, 256>>>(x, Wo, bo, out);
}

// round 3
// speedup vs baseline: 1.3235x; 1.0346x over previous
#include <cuda_runtime.h>
#include <cuda_bf16.h>
#include <math.h>

// Problem constants
#define T_FR 32
#define NN 512
#define FF 256
#define HH 8
#define LL 3
#define DIN 3
#define MAXN 128

#define BM 128
#define BN 64
#define BK 32

// ---------------- scratch (device globals; allocation-free rule) ----------------
__device__ float g_x[T_FR * NN * FF];
__device__ float g_Wh[T_FR * HH * NN * FF];
__device__ float g_xcat[T_FR * NN * HH * FF];
__device__ float g_f[T_FR * HH * NN];
__device__ float g_g[T_FR * HH * NN];
__device__ float g_P[(long)T_FR * HH * NN * MAXN];   // compact attention probs
__device__ int   g_nnz[NN];
__device__ int   g_cols[NN * MAXN];

// ---------------- helpers ----------------
__device__ __forceinline__ void split_bf16(float x, unsigned short& h, unsigned short& l) {
    __nv_bfloat16 bh = __float2bfloat16(x);
    float r = x - __bfloat162float(bh);
    __nv_bfloat16 bl = __float2bfloat16(r);
    h = __bfloat16_as_ushort(bh);
    l = __bfloat16_as_ushort(bl);
}

__device__ __forceinline__ void mma16816(float* c, const unsigned* a, const unsigned* b) {
    asm volatile(
        "mma.sync.aligned.m16n8k16.row.col.f32.bf16.bf16.f32 "
        "{%0,%1,%2,%3}, {%4,%5,%6,%7}, {%8,%9}, {%0,%1,%2,%3};\n"
        : "+f"(c[0]), "+f"(c[1]), "+f"(c[2]), "+f"(c[3])
        : "r"(a[0]), "r"(a[1]), "r"(a[2]), "r"(a[3]), "r"(b[0]), "r"(b[1]));
}

// ---------------- input projection ----------------
__global__ void input_proj_kernel(const float* __restrict__ pose,
                                  const float* __restrict__ Wp,
                                  const float* __restrict__ bp,
                                  float* __restrict__ x) {
    long idx = (long)blockIdx.x * blockDim.x + threadIdx.x;
    if (idx >= (long)T_FR * NN * FF) return;
    int f = (int)(idx % FF);
    long tn = idx / FF;
    const float* p = pose + tn * DIN;
    x[idx] = p[0] * Wp[f] + p[1] * Wp[FF + f] + p[2] * Wp[2 * FF + f] + bp[f];
}

// ---------------- adjacency -> padded neighbor lists ----------------
__global__ void adjlist_kernel(const int* __restrict__ adj,
                               int* __restrict__ nnz, int* __restrict__ cols) {
    __shared__ int cnt;
    int i = blockIdx.x;
    if (threadIdx.x == 0) cnt = 0;
    __syncthreads();
    for (int j = threadIdx.x; j < NN; j += blockDim.x) {
        if (adj[(long)i * NN + j] > 0) {
            int p = atomicAdd(&cnt, 1);
            if (p < MAXN) cols[i * MAXN + p] = j;
        }
    }
    __syncthreads();
    if (threadIdx.x == 0) nnz[i] = (cnt < MAXN) ? cnt : MAXN;
}

// ---------------- bf16 split-3 tensor-core batched GEMM (dense projections) ----------------
__global__ __launch_bounds__(256, 2)
void gemm_mma(const float* __restrict__ A, const float* __restrict__ B,
              float* __restrict__ C,
              int K, int lda, int ldb, int ldc,
              long aStride, int aDiv, long bStride, int bMod,
              long cOuter, int cDiv, long cInner, int epi) {
    int b = blockIdx.z;
    const float* Ab = A + (long)(b / aDiv) * aStride;
    const float* Bb = B + (long)(b % bMod) * bStride;
    float* Cb = C + (long)(b / cDiv) * cOuter + (long)(b % cDiv) * cInner;

    __shared__ __align__(16) unsigned short Ahi[BM][40];
    __shared__ __align__(16) unsigned short Alo[BM][40];
    __shared__ __align__(16) unsigned short Bhi[BN][40];
    __shared__ __align__(16) unsigned short Blo[BN][40];

    int tid = threadIdx.x;
    int lane = tid & 31;
    int warp = tid >> 5;
    int wm = warp & 3;
    int wn = warp >> 2;
    int row0 = blockIdx.y * BM;
    int col0 = blockIdx.x * BN;

    int arow = tid >> 1;
    int acol = (tid & 1) << 4;
    int g = lane >> 2;
    int q = lane & 3;

    float acc[2][4][4];
    #pragma unroll
    for (int i = 0; i < 2; i++)
        #pragma unroll
        for (int j = 0; j < 4; j++)
            #pragma unroll
            for (int k = 0; k < 4; k++) acc[i][j][k] = 0.f;

    for (int k0 = 0; k0 < K; k0 += BK) {
        {
            const float* ap = Ab + (long)(row0 + arow) * lda + k0 + acol;
            #pragma unroll
            for (int i = 0; i < 4; i++) {
                float4 v = *(const float4*)(ap + i * 4);
                unsigned short h0, h1, h2, h3, l0, l1, l2, l3;
                split_bf16(v.x, h0, l0); split_bf16(v.y, h1, l1);
                split_bf16(v.z, h2, l2); split_bf16(v.w, h3, l3);
                int c = acol + i * 4;
                *(unsigned*)&Ahi[arow][c]     = (unsigned)h0 | ((unsigned)h1 << 16);
                *(unsigned*)&Ahi[arow][c + 2] = (unsigned)h2 | ((unsigned)h3 << 16);
                *(unsigned*)&Alo[arow][c]     = (unsigned)l0 | ((unsigned)l1 << 16);
                *(unsigned*)&Alo[arow][c + 2] = (unsigned)l2 | ((unsigned)l3 << 16);
            }
        }
        #pragma unroll
        for (int i = 0; i < 2; i++) {
            int idx4 = tid * 2 + i;
            int krow = idx4 >> 4;
            int ncol = (idx4 & 15) << 2;
            float4 v = *(const float4*)(Bb + (long)(k0 + krow) * ldb + col0 + ncol);
            unsigned short h, l;
            split_bf16(v.x, h, l); Bhi[ncol + 0][krow] = h; Blo[ncol + 0][krow] = l;
            split_bf16(v.y, h, l); Bhi[ncol + 1][krow] = h; Blo[ncol + 1][krow] = l;
            split_bf16(v.z, h, l); Bhi[ncol + 2][krow] = h; Blo[ncol + 2][krow] = l;
            split_bf16(v.w, h, l); Bhi[ncol + 3][krow] = h; Blo[ncol + 3][krow] = l;
        }
        __syncthreads();

        #pragma unroll
        for (int kk = 0; kk < BK; kk += 16) {
            unsigned ah[2][4], al[2][4], bh[4][2], bl[4][2];
            #pragma unroll
            for (int mt = 0; mt < 2; mt++) {
                int r = wm * 32 + mt * 16 + g;
                ah[mt][0] = *(const unsigned*)&Ahi[r][kk + 2 * q];
                ah[mt][1] = *(const unsigned*)&Ahi[r + 8][kk + 2 * q];
                ah[mt][2] = *(const unsigned*)&Ahi[r][kk + 8 + 2 * q];
                ah[mt][3] = *(const unsigned*)&Ahi[r + 8][kk + 8 + 2 * q];
                al[mt][0] = *(const unsigned*)&Alo[r][kk + 2 * q];
                al[mt][1] = *(const unsigned*)&Alo[r + 8][kk + 2 * q];
                al[mt][2] = *(const unsigned*)&Alo[r][kk + 8 + 2 * q];
                al[mt][3] = *(const unsigned*)&Alo[r + 8][kk + 8 + 2 * q];
            }
            #pragma unroll
            for (int nt = 0; nt < 4; nt++) {
                int n = wn * 32 + nt * 8 + g;
                bh[nt][0] = *(const unsigned*)&Bhi[n][kk + 2 * q];
                bh[nt][1] = *(const unsigned*)&Bhi[n][kk + 8 + 2 * q];
                bl[nt][0] = *(const unsigned*)&Blo[n][kk + 2 * q];
                bl[nt][1] = *(const unsigned*)&Blo[n][kk + 8 + 2 * q];
            }
            #pragma unroll
            for (int mt = 0; mt < 2; mt++)
                #pragma unroll
                for (int nt = 0; nt < 4; nt++) mma16816(acc[mt][nt], ah[mt], bh[nt]);
            #pragma unroll
            for (int mt = 0; mt < 2; mt++)
                #pragma unroll
                for (int nt = 0; nt < 4; nt++) mma16816(acc[mt][nt], al[mt], bh[nt]);
            #pragma unroll
            for (int mt = 0; mt < 2; mt++)
                #pragma unroll
                for (int nt = 0; nt < 4; nt++) mma16816(acc[mt][nt], ah[mt], bl[nt]);
        }
        __syncthreads();
    }

    #pragma unroll
    for (int mt = 0; mt < 2; mt++) {
        #pragma unroll
        for (int nt = 0; nt < 4; nt++) {
            int r = row0 + wm * 32 + mt * 16 + g;
            int c = col0 + wn * 32 + nt * 8 + 2 * q;
            float vv[4] = {acc[mt][nt][0], acc[mt][nt][1], acc[mt][nt][2], acc[mt][nt][3]};
            #pragma unroll
            for (int j = 0; j < 4; j++) {
                float u = vv[j];
                if (epi >= 1) u = (u >= 0.f) ? u : expm1f(u);
                if (epi == 2) u = (u >= 0.f) ? u : expm1f(u);
                vv[j] = u;
            }
            *(float2*)&Cb[(long)r * ldc + c] = make_float2(vv[0], vv[1]);
            *(float2*)&Cb[(long)(r + 8) * ldc + c] = make_float2(vv[2], vv[3]);
        }
    }
}

// ---------------- f/g terms (one warp per row) ----------------
__global__ void fg_kernel(const float* __restrict__ Wh, const float* __restrict__ a,
                          int aMod, float* __restrict__ f, float* __restrict__ g,
                          int batches) {
    long w = ((long)blockIdx.x * blockDim.x + threadIdx.x) >> 5;
    int lane = threadIdx.x & 31;
    if (w >= (long)batches * NN) return;
    int b = (int)(w / NN);
    const float* row = Wh + w * FF;
    const float* ar = a + (long)(b % aMod) * (2 * FF);
    float s1 = 0.f, s2 = 0.f;
    #pragma unroll
    for (int i = 0; i < FF / 32; i++) {
        float v = row[lane + 32 * i];
        s1 += v * ar[lane + 32 * i];
        s2 += v * ar[FF + lane + 32 * i];
    }
    #pragma unroll
    for (int o = 16; o > 0; o >>= 1) {
        s1 += __shfl_down_sync(0xffffffffu, s1, o);
        s2 += __shfl_down_sync(0xffffffffu, s2, o);
    }
    if (lane == 0) { f[w] = s1; g[w] = s2; }
}

// ---------------- sparse softmax over neighbor lists (one warp per row) ----------------
__global__ void softmax_sparse_kernel(const float* __restrict__ f, const float* __restrict__ g,
                                      const int* __restrict__ nnz, const int* __restrict__ cols,
                                      float* __restrict__ Pc, int totalRows) {
    int w = (int)(((long)blockIdx.x * blockDim.x + threadIdx.x) >> 5);
    int lane = threadIdx.x & 31;
    if (w >= totalRows) return;
    int b = w >> 9;                  // w / NN
    int i = w & 511;                 // w % NN
    float fi = f[w];
    const float* gb = g + (long)b * NN;
    int n = nnz[i];
    const int* crow = cols + i * MAXN;
    int nc = (n + 31) >> 5;

    float e[4];
    float mx = -INFINITY;
    for (int c = 0; c < nc; c++) {
        int k = c * 32 + lane;
        float v = -INFINITY;
        if (k < n) {
            float xv = fi + gb[crow[k]];
            v = (xv >= 0.f) ? xv : 0.2f * xv;
        }
        e[c] = v;
        mx = fmaxf(mx, v);
    }
    #pragma unroll
    for (int o = 16; o > 0; o >>= 1) mx = fmaxf(mx, __shfl_xor_sync(0xffffffffu, mx, o));

    float s = 0.f;
    for (int c = 0; c < nc; c++) {
        float ev = (e[c] > -1e30f) ? __expf(e[c] - mx) : 0.f;
        e[c] = ev; s += ev;
    }
    #pragma unroll
    for (int o = 16; o > 0; o >>= 1) s += __shfl_xor_sync(0xffffffffu, s, o);
    float inv = 1.0f / s;

    float* prow = Pc + (long)w * MAXN;
    for (int c = 0; c < nc; c++) {
        int k = c * 32 + lane;
        if (k < n) prow[k] = e[c] * inv;
    }
}

// ---------------- sparse attention apply: C[i,:] = epi( sum_k P[i,k] * Wh[col[i,k],:] ) ----------------
// grid = (FF/64, batches); smem caches Wh[:, chunk] (512 x 64 fp32 = 128KB)
__global__ __launch_bounds__(256)
void spmm_kernel(const float* __restrict__ Pc, const float* __restrict__ Wh,
                 const int* __restrict__ nnz, const int* __restrict__ cols,
                 float* __restrict__ C,
                 long whStride, long cOuter, int cDiv, long cInner, int ldc, int epi) {
    extern __shared__ float WhS[];   // [NN][64]
    int b = blockIdx.y;
    int c0 = blockIdx.x * 64;
    const float* Whb = Wh + (long)b * whStride;
    float* Cb = C + (long)(b / cDiv) * cOuter + (long)(b % cDiv) * cInner;

    for (int idx = threadIdx.x; idx < NN * 16; idx += 256) {
        int row = idx >> 4;
        int col4 = (idx & 15) << 2;
        *(float4*)&WhS[row * 64 + col4] =
            *(const float4*)&Whb[(long)row * FF + c0 + col4];
    }
    __syncthreads();

    int warp = threadIdx.x >> 5;
    int lane = threadIdx.x & 31;
    for (int i = warp; i < NN; i += 8) {
        int n = nnz[i];
        const int* crow = cols + i * MAXN;
        const float* prow = Pc + ((long)b * NN + i) * MAXN;
        float ax = 0.f, ay = 0.f;
        #pragma unroll 4
        for (int k = 0; k < n; k++) {
            int j = crow[k];          // uniform load (L1 broadcast)
            float wv = prow[k];       // uniform load
            float2 v = *(const float2*)&WhS[j * 64 + 2 * lane];
            ax += wv * v.x; ay += wv * v.y;
        }
        if (epi >= 1) { ax = ax >= 0.f ? ax : expm1f(ax); ay = ay >= 0.f ? ay : expm1f(ay); }
        if (epi == 2) { ax = ax >= 0.f ? ax : expm1f(ax); ay = ay >= 0.f ? ay : expm1f(ay); }
        *(float2*)&Cb[(long)i * ldc + c0 + 2 * lane] = make_float2(ax, ay);
    }
}

// ---------------- final pool ----------------
__global__ void pool_kernel(const float* __restrict__ x, const float* __restrict__ Wo,
                            const float* __restrict__ bo, float* __restrict__ out) {
    int t = blockIdx.x;
    int f = threadIdx.x;
    __shared__ float m[FF];
    const float* xt = x + (long)t * NN * FF;
    float s = 0.f;
    for (int n = 0; n < NN; n++) s += xt[n * FF + f];
    m[f] = s * (1.0f / NN);
    __syncthreads();
    float o = bo[f];
    for (int k = 0; k < FF; k++) o += m[k] * Wo[k * FF + f];
    out[t * FF + f] = o;
}

// ---------------- host orchestration ----------------
extern "C" void kernel_launch(void* const* d_in, const int* in_sizes, int n_in,
                              void* d_out, int out_size) {
    const float* pose    = (const float*)d_in[0];
    const int*   adj     = (const int*)  d_in[1];
    const float* Wp      = (const float*)d_in[2];
    const float* bp      = (const float*)d_in[3];
    const float* W_heads = (const float*)d_in[4];
    const float* a_heads = (const float*)d_in[5];
    const float* W_out   = (const float*)d_in[6];
    const float* a_out   = (const float*)d_in[7];
    const float* Wo      = (const float*)d_in[8];
    const float* bo      = (const float*)d_in[9];
    float* out = (float*)d_out;

    float *x, *Wh, *xcat, *fb, *gb, *P;
    int *nnz, *colsArr;
    cudaGetSymbolAddress((void**)&x,    g_x);
    cudaGetSymbolAddress((void**)&Wh,   g_Wh);
    cudaGetSymbolAddress((void**)&xcat, g_xcat);
    cudaGetSymbolAddress((void**)&fb,   g_f);
    cudaGetSymbolAddress((void**)&gb,   g_g);
    cudaGetSymbolAddress((void**)&P,    g_P);
    cudaGetSymbolAddress((void**)&nnz,  g_nnz);
    cudaGetSymbolAddress((void**)&colsArr, g_cols);

    static bool smemSet = false;
    if (!smemSet) {
        cudaFuncSetAttribute(spmm_kernel,
                             cudaFuncAttributeMaxDynamicSharedMemorySize, NN * 64 * 4);
        smemSet = true;
    }

    adjlist_kernel<<<NN, 256>>>(adj, nnz, colsArr);

    {
        long total = (long)T_FR * NN * FF;
        input_proj_kernel<<<(unsigned)((total + 255) / 256), 256>>>(pose, Wp, bp, x);
    }

    for (int l = 0; l < LL; l++) {
        const float* Wl  = W_heads + (long)l * HH * FF * FF;
        const float* al  = a_heads + (long)l * HH * 2 * FF;
        const float* Wol = W_out   + (long)l * (HH * FF) * FF;
        const float* aol = a_out   + (long)l * 2 * FF;

        // 2a. Wh[t,h] = x[t] @ W_heads[l,h]  (dense, tensor cores)
        {
            dim3 grid(FF / BN, NN / BM, T_FR * HH);
            gemm_mma<<<grid, 256>>>(x, Wl, Wh,
                FF, FF, FF, FF,
                (long)NN * FF, HH,
                (long)FF * FF, HH,
                (long)NN * FF, 1, 0,
                0);
        }
        // 2b. f,g per head
        {
            long warps = (long)T_FR * HH * NN;
            fg_kernel<<<(unsigned)((warps * 32 + 255) / 256), 256>>>(Wh, al, HH, fb, gb, T_FR * HH);
        }
        // 2c. sparse softmax -> compact P
        {
            int rows = T_FR * HH * NN;
            softmax_sparse_kernel<<<(rows * 32 + 255) / 256, 256>>>(fb, gb, nnz, colsArr, P, rows);
        }
        // 2d. xcat[t][:, h*F:(h+1)*F] = elu(P @ Wh)  (sparse gather)
        {
            dim3 grid(FF / 64, T_FR * HH);
            spmm_kernel<<<grid, 256, NN * 64 * 4>>>(P, Wh, nnz, colsArr, xcat,
                (long)NN * FF,
                (long)NN * HH * FF, HH, FF, HH * FF, 1);
        }
        // 2e. Whout[t] = xcat[t] @ W_out[l]  (dense, tensor cores)
        {
            dim3 grid(FF / BN, NN / BM, T_FR);
            gemm_mma<<<grid, 256>>>(xcat, Wol, Wh,
                HH * FF, HH * FF, FF, FF,
                (long)NN * HH * FF, 1,
                0, 1,
                (long)NN * FF, 1, 0,
                0);
        }
        // 2f. f,g for out-head
        {
            long warps = (long)T_FR * NN;
            fg_kernel<<<(unsigned)((warps * 32 + 255) / 256), 256>>>(Wh, aol, 1, fb, gb, T_FR);
        }
        // 2g. sparse softmax -> compact P
        {
            int rows = T_FR * NN;
            softmax_sparse_kernel<<<(rows * 32 + 255) / 256, 256>>>(fb, gb, nnz, colsArr, P, rows);
        }
        // 2h. x[t] = elu(elu(P @ Whout))  (sparse gather)
        {
            dim3 grid(FF / 64, T_FR);
            spmm_kernel<<<grid, 256, NN * 64 * 4>>>(P, Wh, nnz, colsArr, x,
                (long)NN * FF,
                (long)NN * FF, 1, 0, FF, 2);
        }
    }

    pool_kernel<<<T_FR, 256>>>(x, Wo, bo, out);
}

// round 5
// speedup vs baseline: 1.5364x; 1.1608x over previous
#include <cuda_runtime.h>
#include <cuda_fp16.h>
#include <math.h>
#include <stdint.h>

// Problem constants
#define T_FR 32
#define NN 512
#define FF 256
#define HH 8
#define LL 3
#define DIN 3
#define MAXN 128

// ---------------- scratch (device globals; allocation-free rule) ----------------
__device__ float  g_x[T_FR * NN * FF];                    // fp32 features (pool input)
__device__ float  g_Wh[T_FR * HH * NN * FF];              // per-head Wh fp32 (reused)
__device__ __half g_xh[T_FR * NN * FF];                   // x hi
__device__ __half g_xl[T_FR * NN * FF];                   // x lo
__device__ __half g_xch[T_FR * NN * HH * FF];             // xcat hi
__device__ __half g_xcl[T_FR * NN * HH * FF];             // xcat lo
__device__ __half g_Wth[LL * HH * FF * FF];               // W_heads^T hi  [l][h][n][k]
__device__ __half g_Wtl[LL * HH * FF * FF];               // W_heads^T lo
__device__ __half g_Woth[LL * FF * HH * FF];              // W_out^T hi    [l][n=256][k=2048]
__device__ __half g_Wotl[LL * FF * HH * FF];              // W_out^T lo
__device__ float  g_f[T_FR * HH * NN];
__device__ float  g_g[T_FR * HH * NN];
__device__ float  g_P[(long)T_FR * HH * NN * MAXN];
__device__ int    g_nnz[NN];
__device__ int    g_cols[NN * MAXN];

// ---------------- helpers ----------------
__device__ __forceinline__ void split_h(float x, __half& h, __half& l) {
    h = __float2half_rn(x);
    l = __float2half_rn(x - __half2float(h));
}
__device__ __forceinline__ uint32_t smem_u32(const void* p) {
    uint32_t a;
    asm("{ .reg .u64 t; cvta.to.shared.u64 t, %1; cvt.u32.u64 %0, t; }" : "=r"(a) : "l"(p));
    return a;
}
__device__ __forceinline__ void cp16(uint32_t dst, const void* src) {
    asm volatile("cp.async.cg.shared.global [%0], [%1], 16;" :: "r"(dst), "l"(src));
}
__device__ __forceinline__ void ldsm4(uint32_t* r, uint32_t addr) {
    asm volatile("ldmatrix.sync.aligned.m8n8.x4.shared.b16 {%0,%1,%2,%3}, [%4];"
        : "=r"(r[0]), "=r"(r[1]), "=r"(r[2]), "=r"(r[3]) : "r"(addr));
}
__device__ __forceinline__ void mma_fp16(float* c, const uint32_t* a, const uint32_t* b) {
    asm volatile("mma.sync.aligned.m16n8k16.row.col.f32.f16.f16.f32 "
        "{%0,%1,%2,%3}, {%4,%5,%6,%7}, {%8,%9}, {%0,%1,%2,%3};"
        : "+f"(c[0]), "+f"(c[1]), "+f"(c[2]), "+f"(c[3])
        : "r"(a[0]), "r"(a[1]), "r"(a[2]), "r"(a[3]), "r"(b[0]), "r"(b[1]));
}

// ---------------- input projection -> fp16 hi/lo ----------------
__global__ void input_proj_kernel(const float* __restrict__ pose,
                                  const float* __restrict__ Wp,
                                  const float* __restrict__ bp,
                                  __half* __restrict__ xh, __half* __restrict__ xl) {
    long idx = (long)blockIdx.x * blockDim.x + threadIdx.x;
    if (idx >= (long)T_FR * NN * FF) return;
    int f = (int)(idx % FF);
    long tn = idx / FF;
    const float* p = pose + tn * DIN;
    float v = p[0] * Wp[f] + p[1] * Wp[FF + f] + p[2] * Wp[2 * FF + f] + bp[f];
    __half h, l; split_h(v, h, l);
    xh[idx] = h; xl[idx] = l;
}

// ---------------- weight transpose + split: W [K][N] fp32 -> Wt hi/lo [N][K] fp16 ----------------
__global__ void wsplit_kernel(const float* __restrict__ W,
                              __half* __restrict__ hi, __half* __restrict__ lo,
                              int K, int N) {
    __shared__ float tile[32][33];
    int b = blockIdx.z;
    const float* Wb = W + (long)b * K * N;
    __half* hb = hi + (long)b * K * N;
    __half* lb = lo + (long)b * K * N;
    int kb = blockIdx.y * 32, nb = blockIdx.x * 32;
    for (int r = threadIdx.y; r < 32; r += 8)
        tile[r][threadIdx.x] = Wb[(long)(kb + r) * N + nb + threadIdx.x];
    __syncthreads();
    for (int r = threadIdx.y; r < 32; r += 8) {
        float v = tile[threadIdx.x][r];            // = W[kb+tx][nb+r]
        __half h, l; split_h(v, h, l);
        long o = (long)(nb + r) * K + kb + threadIdx.x;
        hb[o] = h; lb[o] = l;
    }
}

// ---------------- adjacency -> padded neighbor lists ----------------
__global__ void adjlist_kernel(const int* __restrict__ adj,
                               int* __restrict__ nnz, int* __restrict__ cols) {
    __shared__ int cnt;
    int i = blockIdx.x;
    if (threadIdx.x == 0) cnt = 0;
    __syncthreads();
    for (int j = threadIdx.x; j < NN; j += blockDim.x) {
        if (adj[(long)i * NN + j] > 0) {
            int p = atomicAdd(&cnt, 1);
            if (p < MAXN) cols[i * MAXN + p] = j;
        }
    }
    __syncthreads();
    if (threadIdx.x == 0) nnz[i] = (cnt < MAXN) ? cnt : MAXN;
}

// ============================================================================
// fp16 split-3 tensor-core GEMM on pre-split operands.
// C = A@B^T(layout): A hi/lo [M][K] fp16, B hi/lo [N][K] fp16 (pre-transposed).
// CTA tile 128x64, warp tile 32x32 (8 warps = 4m x 2n), BK=32, cp.async loads.
// ============================================================================
#define AHI 0
#define ALO 5120
#define BHI 10240
#define BLO 12800

__global__ __launch_bounds__(256)
void gemm_tc(const __half* __restrict__ Ah, const __half* __restrict__ Al,
             const __half* __restrict__ Bh, const __half* __restrict__ Bl,
             float* __restrict__ C,
             int K, int lda, int ldb, int ldc,
             long aStride, int aDiv, long bStride, int bMod,
             long cOuter, int cDiv, long cInner, int epi) {
    __shared__ __align__(16) unsigned short sm[15360];
    uint32_t sb = smem_u32(sm);

    int tid = threadIdx.x;
    int lane = tid & 31;
    int warp = tid >> 5;
    int wm = warp >> 1;        // 0..3 -> m offset wm*32
    int wn = warp & 1;         // 0..1 -> n offset wn*32
    int g = lane >> 2;
    int q = lane & 3;

    int b = blockIdx.z;
    int col0 = blockIdx.x * 64;
    int row0 = blockIdx.y * 128;
    const __half* AhB = Ah + (long)(b / aDiv) * aStride;
    const __half* AlB = Al + (long)(b / aDiv) * aStride;
    const __half* BhB = Bh + (long)(b % bMod) * bStride;
    const __half* BlB = Bl + (long)(b % bMod) * bStride;
    float* Cb = C + (long)(b / cDiv) * cOuter + (long)(b % cDiv) * cInner;

    float acc[2][4][4];
    #pragma unroll
    for (int i = 0; i < 2; i++)
        #pragma unroll
        for (int j = 0; j < 4; j++)
            #pragma unroll
            for (int k = 0; k < 4; k++) acc[i][j][k] = 0.f;

    // per-thread copy slots
    int arow0 = tid >> 2, aseg = tid & 3;          // A: rows 0..63 (+64 second)
    int brow = tid >> 2, bseg = tid & 3;           // B: rows 0..63

    // ldmatrix lane addresses (k part added in loop)
    int aRowA = (lane & 15);
    int kHalf = (lane >> 4) << 3;

    for (int k0 = 0; k0 < K; k0 += 32) {
        // A hi/lo: 128 rows x 32 halfs (4 segs of 8)
        #pragma unroll
        for (int h = 0; h < 2; h++) {
            int row = arow0 + h * 64;
            uint32_t d = sb + (uint32_t)((row * 40 + aseg * 8) * 2);
            const __half* sa = AhB + (long)(row0 + row) * lda + k0 + aseg * 8;
            cp16(d + AHI * 2, sa);
            cp16(d + ALO * 2, AlB + (long)(row0 + row) * lda + k0 + aseg * 8);
        }
        // B hi/lo: 64 rows x 32 halfs
        {
            uint32_t d = sb + (uint32_t)((brow * 40 + bseg * 8) * 2);
            cp16(d + BHI * 2, BhB + (long)(col0 + brow) * ldb + k0 + bseg * 8);
            cp16(d + BLO * 2, BlB + (long)(col0 + brow) * ldb + k0 + bseg * 8);
        }
        asm volatile("cp.async.commit_group;");
        asm volatile("cp.async.wait_group 0;");
        __syncthreads();

        #pragma unroll
        for (int kk = 0; kk < 32; kk += 16) {
            uint32_t ah[2][4], al[2][4], bhf[4][2], blf[4][2];
            #pragma unroll
            for (int mt = 0; mt < 2; mt++) {
                uint32_t addr = sb + (uint32_t)(((AHI) + (wm * 32 + mt * 16 + aRowA) * 40 + kk + kHalf) * 2);
                ldsm4(ah[mt], addr);
                ldsm4(al[mt], addr + (ALO - AHI) * 2);
            }
            #pragma unroll
            for (int ng = 0; ng < 2; ng++) {
                uint32_t r[4];
                uint32_t addr = sb + (uint32_t)(((BHI) + (wn * 32 + ng * 16 + aRowA) * 40 + kk + kHalf) * 2);
                ldsm4(r, addr);
                bhf[ng * 2 + 0][0] = r[0]; bhf[ng * 2 + 0][1] = r[2];
                bhf[ng * 2 + 1][0] = r[1]; bhf[ng * 2 + 1][1] = r[3];
                ldsm4(r, addr + (BLO - BHI) * 2);
                blf[ng * 2 + 0][0] = r[0]; blf[ng * 2 + 0][1] = r[2];
                blf[ng * 2 + 1][0] = r[1]; blf[ng * 2 + 1][1] = r[3];
            }
            #pragma unroll
            for (int mt = 0; mt < 2; mt++)
                #pragma unroll
                for (int nt = 0; nt < 4; nt++) mma_fp16(acc[mt][nt], ah[mt], bhf[nt]);
            #pragma unroll
            for (int mt = 0; mt < 2; mt++)
                #pragma unroll
                for (int nt = 0; nt < 4; nt++) mma_fp16(acc[mt][nt], al[mt], bhf[nt]);
            #pragma unroll
            for (int mt = 0; mt < 2; mt++)
                #pragma unroll
                for (int nt = 0; nt < 4; nt++) mma_fp16(acc[mt][nt], ah[mt], blf[nt]);
        }
        __syncthreads();
    }

    // epilogue
    #pragma unroll
    for (int mt = 0; mt < 2; mt++) {
        #pragma unroll
        for (int nt = 0; nt < 4; nt++) {
            int r = row0 + wm * 32 + mt * 16 + g;
            int c = col0 + wn * 32 + nt * 8 + 2 * q;
            float vv[4] = {acc[mt][nt][0], acc[mt][nt][1], acc[mt][nt][2], acc[mt][nt][3]};
            #pragma unroll
            for (int j = 0; j < 4; j++) {
                float u = vv[j];
                if (epi >= 1) u = (u >= 0.f) ? u : expm1f(u);
                if (epi == 2) u = (u >= 0.f) ? u : expm1f(u);
                vv[j] = u;
            }
            *(float2*)&Cb[(long)r * ldc + c] = make_float2(vv[0], vv[1]);
            *(float2*)&Cb[(long)(r + 8) * ldc + c] = make_float2(vv[2], vv[3]);
        }
    }
}

// ---------------- f/g terms (one warp per row) ----------------
__global__ void fg_kernel(const float* __restrict__ Wh, const float* __restrict__ a,
                          int aMod, float* __restrict__ f, float* __restrict__ g,
                          int batches) {
    long w = ((long)blockIdx.x * blockDim.x + threadIdx.x) >> 5;
    int lane = threadIdx.x & 31;
    if (w >= (long)batches * NN) return;
    int b = (int)(w / NN);
    const float* row = Wh + w * FF;
    const float* ar = a + (long)(b % aMod) * (2 * FF);
    float s1 = 0.f, s2 = 0.f;
    #pragma unroll
    for (int i = 0; i < FF / 32; i++) {
        float v = row[lane + 32 * i];
        s1 += v * ar[lane + 32 * i];
        s2 += v * ar[FF + lane + 32 * i];
    }
    #pragma unroll
    for (int o = 16; o > 0; o >>= 1) {
        s1 += __shfl_down_sync(0xffffffffu, s1, o);
        s2 += __shfl_down_sync(0xffffffffu, s2, o);
    }
    if (lane == 0) { f[w] = s1; g[w] = s2; }
}

// ---------------- sparse softmax over neighbor lists ----------------
__global__ void softmax_sparse_kernel(const float* __restrict__ f, const float* __restrict__ g,
                                      const int* __restrict__ nnz, const int* __restrict__ cols,
                                      float* __restrict__ Pc, int totalRows) {
    int w = (int)(((long)blockIdx.x * blockDim.x + threadIdx.x) >> 5);
    int lane = threadIdx.x & 31;
    if (w >= totalRows) return;
    int b = w >> 9;
    int i = w & 511;
    float fi = f[w];
    const float* gb = g + (long)b * NN;
    int n = nnz[i];
    const int* crow = cols + i * MAXN;
    int nc = (n + 31) >> 5;

    float e[4];
    float mx = -INFINITY;
    for (int c = 0; c < nc; c++) {
        int k = c * 32 + lane;
        float v = -INFINITY;
        if (k < n) {
            float xv = fi + gb[crow[k]];
            v = (xv >= 0.f) ? xv : 0.2f * xv;
        }
        e[c] = v;
        mx = fmaxf(mx, v);
    }
    #pragma unroll
    for (int o = 16; o > 0; o >>= 1) mx = fmaxf(mx, __shfl_xor_sync(0xffffffffu, mx, o));

    float s = 0.f;
    for (int c = 0; c < nc; c++) {
        float ev = (e[c] > -1e30f) ? __expf(e[c] - mx) : 0.f;
        e[c] = ev; s += ev;
    }
    #pragma unroll
    for (int o = 16; o > 0; o >>= 1) s += __shfl_xor_sync(0xffffffffu, s, o);
    float inv = 1.0f / s;

    float* prow = Pc + (long)w * MAXN;
    for (int c = 0; c < nc; c++) {
        int k = c * 32 + lane;
        if (k < n) prow[k] = e[c] * inv;
    }
}

// ---------------- sparse attention apply; writes fp16 hi/lo (+ optional fp32) ----------------
__global__ __launch_bounds__(256)
void spmm_kernel(const float* __restrict__ Pc, const float* __restrict__ Wh,
                 const int* __restrict__ nnz, const int* __restrict__ cols,
                 __half* __restrict__ Chi, __half* __restrict__ Clo,
                 float* __restrict__ Cf, int writeF,
                 long whStride, long cOuter, int cDiv, long cInner, int ldc, int epi) {
    extern __shared__ float WhS[];
    int b = blockIdx.y;
    int c0 = blockIdx.x * 64;
    const float* Whb = Wh + (long)b * whStride;
    long cOff = (long)(b / cDiv) * cOuter + (long)(b % cDiv) * cInner;

    for (int idx = threadIdx.x; idx < NN * 16; idx += 256) {
        int row = idx >> 4;
        int col4 = (idx & 15) << 2;
        *(float4*)&WhS[row * 64 + col4] =
            *(const float4*)&Whb[(long)row * FF + c0 + col4];
    }
    __syncthreads();

    int warp = threadIdx.x >> 5;
    int lane = threadIdx.x & 31;
    for (int i = warp; i < NN; i += 8) {
        int n = nnz[i];
        const int* crow = cols + i * MAXN;
        const float* prow = Pc + ((long)b * NN + i) * MAXN;
        float ax = 0.f, ay = 0.f;
        #pragma unroll 4
        for (int k = 0; k < n; k++) {
            int j = crow[k];
            float wv = prow[k];
            float2 v = *(const float2*)&WhS[j * 64 + 2 * lane];
            ax += wv * v.x; ay += wv * v.y;
        }
        if (epi >= 1) { ax = ax >= 0.f ? ax : expm1f(ax); ay = ay >= 0.f ? ay : expm1f(ay); }
        if (epi == 2) { ax = ax >= 0.f ? ax : expm1f(ax); ay = ay >= 0.f ? ay : expm1f(ay); }
        long o = cOff + (long)i * ldc + c0 + 2 * lane;
        __half hx, lx, hy, ly;
        split_h(ax, hx, lx); split_h(ay, hy, ly);
        __half2 hv; hv.x = hx; hv.y = hy;
        __half2 lv; lv.x = lx; lv.y = ly;
        *(__half2*)&Chi[o] = hv;
        *(__half2*)&Clo[o] = lv;
        if (writeF) *(float2*)&Cf[o] = make_float2(ax, ay);
    }
}

// ---------------- final pool ----------------
__global__ void pool_kernel(const float* __restrict__ x, const float* __restrict__ Wo,
                            const float* __restrict__ bo, float* __restrict__ out) {
    int t = blockIdx.x;
    int f = threadIdx.x;
    __shared__ float m[FF];
    const float* xt = x + (long)t * NN * FF;
    float s = 0.f;
    for (int n = 0; n < NN; n++) s += xt[n * FF + f];
    m[f] = s * (1.0f / NN);
    __syncthreads();
    float o = bo[f];
    for (int k = 0; k < FF; k++) o += m[k] * Wo[k * FF + f];
    out[t * FF + f] = o;
}

// ---------------- host orchestration ----------------
extern "C" void kernel_launch(void* const* d_in, const int* in_sizes, int n_in,
                              void* d_out, int out_size) {
    const float* pose    = (const float*)d_in[0];
    const int*   adj     = (const int*)  d_in[1];
    const float* Wp      = (const float*)d_in[2];
    const float* bp      = (const float*)d_in[3];
    const float* W_heads = (const float*)d_in[4];
    const float* a_heads = (const float*)d_in[5];
    const float* W_out   = (const float*)d_in[6];
    const float* a_out   = (const float*)d_in[7];
    const float* Wo      = (const float*)d_in[8];
    const float* bo      = (const float*)d_in[9];
    float* out = (float*)d_out;

    float *x, *Wh, *fb, *gb, *P;
    __half *xh, *xl, *xch, *xcl, *Wth, *Wtl, *Woth, *Wotl;
    int *nnz, *colsArr;
    cudaGetSymbolAddress((void**)&x,    g_x);
    cudaGetSymbolAddress((void**)&Wh,   g_Wh);
    cudaGetSymbolAddress((void**)&xh,   g_xh);
    cudaGetSymbolAddress((void**)&xl,   g_xl);
    cudaGetSymbolAddress((void**)&xch,  g_xch);
    cudaGetSymbolAddress((void**)&xcl,  g_xcl);
    cudaGetSymbolAddress((void**)&Wth,  g_Wth);
    cudaGetSymbolAddress((void**)&Wtl,  g_Wtl);
    cudaGetSymbolAddress((void**)&Woth, g_Woth);
    cudaGetSymbolAddress((void**)&Wotl, g_Wotl);
    cudaGetSymbolAddress((void**)&fb,   g_f);
    cudaGetSymbolAddress((void**)&gb,   g_g);
    cudaGetSymbolAddress((void**)&P,    g_P);
    cudaGetSymbolAddress((void**)&nnz,  g_nnz);
    cudaGetSymbolAddress((void**)&colsArr, g_cols);

    static bool attrSet = false;
    if (!attrSet) {
        cudaFuncSetAttribute(spmm_kernel,
                             cudaFuncAttributeMaxDynamicSharedMemorySize, NN * 64 * 4);
        attrSet = true;
    }

    adjlist_kernel<<<NN, 256>>>(adj, nnz, colsArr);

    // weight transpose+split (all layers)
    {
        dim3 blk(32, 8);
        dim3 gh(FF / 32, FF / 32, LL * HH);
        wsplit_kernel<<<gh, blk>>>(W_heads, Wth, Wtl, FF, FF);
        dim3 go(FF / 32, (HH * FF) / 32, LL);
        wsplit_kernel<<<go, blk>>>(W_out, Woth, Wotl, HH * FF, FF);
    }

    {
        long total = (long)T_FR * NN * FF;
        input_proj_kernel<<<(unsigned)((total + 255) / 256), 256>>>(pose, Wp, bp, xh, xl);
    }

    for (int l = 0; l < LL; l++) {
        const __half* Wlh = Wth  + (long)l * HH * FF * FF;
        const __half* Wll = Wtl  + (long)l * HH * FF * FF;
        const __half* Woh = Woth + (long)l * FF * HH * FF;
        const __half* Wol = Wotl + (long)l * FF * HH * FF;
        const float* al  = a_heads + (long)l * HH * 2 * FF;
        const float* aol = a_out   + (long)l * 2 * FF;

        // 2a. Wh[t,h] = x[t] @ W_heads[l,h]   (fp16 split-3, K=256)
        {
            dim3 grid(FF / 64, NN / 128, T_FR * HH);
            gemm_tc<<<grid, 256>>>(xh, xl, Wlh, Wll, Wh,
                FF, FF, FF, FF,
                (long)NN * FF, HH,
                (long)FF * FF, HH,
                (long)NN * FF, 1, 0,
                0);
        }
        // 2b. f,g per head
        {
            long warps = (long)T_FR * HH * NN;
            fg_kernel<<<(unsigned)((warps * 32 + 255) / 256), 256>>>(Wh, al, HH, fb, gb, T_FR * HH);
        }
        // 2c. sparse softmax -> compact P
        {
            int rows = T_FR * HH * NN;
            softmax_sparse_kernel<<<(rows * 32 + 255) / 256, 256>>>(fb, gb, nnz, colsArr, P, rows);
        }
        // 2d. xcat = elu(P @ Wh)  -> fp16 hi/lo
        {
            dim3 grid(FF / 64, T_FR * HH);
            spmm_kernel<<<grid, 256, NN * 64 * 4>>>(P, Wh, nnz, colsArr,
                xch, xcl, (float*)0, 0,
                (long)NN * FF,
                (long)NN * HH * FF, HH, FF, HH * FF, 1);
        }
        // 2e. Whout[t] = xcat[t] @ W_out[l]  (fp16 split-3, K=2048)
        {
            dim3 grid(FF / 64, NN / 128, T_FR);
            gemm_tc<<<grid, 256>>>(xch, xcl, Woh, Wol, Wh,
                HH * FF, HH * FF, HH * FF, FF,
                (long)NN * HH * FF, 1,
                0, 1,
                (long)NN * FF, 1, 0,
                0);
        }
        // 2f. f,g for out-head
        {
            long warps = (long)T_FR * NN;
            fg_kernel<<<(unsigned)((warps * 32 + 255) / 256), 256>>>(Wh, aol, 1, fb, gb, T_FR);
        }
        // 2g. sparse softmax -> compact P
        {
            int rows = T_FR * NN;
            softmax_sparse_kernel<<<(rows * 32 + 255) / 256, 256>>>(fb, gb, nnz, colsArr, P, rows);
        }
        // 2h. x = elu(elu(P @ Whout))  -> fp32 (pool) + fp16 hi/lo (next layer)
        {
            dim3 grid(FF / 64, T_FR);
            spmm_kernel<<<grid, 256, NN * 64 * 4>>>(P, Wh, nnz, colsArr,
                xh, xl, x, 1,
                (long)NN * FF,
                (long)NN * FF, 1, 0, FF, 2);
        }
    }

    pool_kernel<<<T_FR, 256>>>(x, Wo, bo, out);
}

// round 6
// speedup vs baseline: 1.5483x; 1.0078x over previous
#include <cuda_runtime.h>
#include <cuda_fp16.h>
#include <math.h>
#include <stdint.h>

// Problem constants
#define T_FR 32
#define NN 512
#define FF 256
#define HH 8
#define LL 3
#define DIN 3
#define MAXN 128

// ---------------- scratch (device globals; allocation-free rule) ----------------
__device__ float  g_x[T_FR * NN * FF];
__device__ float  g_Wh[T_FR * HH * NN * FF];
__device__ __half g_xh[T_FR * NN * FF];
__device__ __half g_xl[T_FR * NN * FF];
__device__ __half g_xch[T_FR * NN * HH * FF];
__device__ __half g_xcl[T_FR * NN * HH * FF];
__device__ __half g_Wth[LL * HH * FF * FF];
__device__ __half g_Wtl[LL * HH * FF * FF];
__device__ __half g_Woth[LL * FF * HH * FF];
__device__ __half g_Wotl[LL * FF * HH * FF];
__device__ float  g_f[T_FR * HH * NN];
__device__ float  g_g[T_FR * HH * NN];
__device__ float  g_P[(long)T_FR * HH * NN * MAXN];
__device__ int    g_nnz[NN];
__device__ int    g_cols[NN * MAXN];

// ---------------- helpers ----------------
__device__ __forceinline__ void split_h(float x, __half& h, __half& l) {
    h = __float2half_rn(x);
    l = __float2half_rn(x - __half2float(h));
}
__device__ __forceinline__ uint32_t smem_u32(const void* p) {
    uint32_t a;
    asm("{ .reg .u64 t; cvta.to.shared.u64 t, %1; cvt.u32.u64 %0, t; }" : "=r"(a) : "l"(p));
    return a;
}
__device__ __forceinline__ void cp16(uint32_t dst, const void* src) {
    asm volatile("cp.async.cg.shared.global [%0], [%1], 16;" :: "r"(dst), "l"(src));
}
__device__ __forceinline__ void ldsm4(uint32_t* r, uint32_t addr) {
    asm volatile("ldmatrix.sync.aligned.m8n8.x4.shared.b16 {%0,%1,%2,%3}, [%4];"
        : "=r"(r[0]), "=r"(r[1]), "=r"(r[2]), "=r"(r[3]) : "r"(addr));
}
__device__ __forceinline__ void mma_fp16(float* c, const uint32_t* a, const uint32_t* b) {
    asm volatile("mma.sync.aligned.m16n8k16.row.col.f32.f16.f16.f32 "
        "{%0,%1,%2,%3}, {%4,%5,%6,%7}, {%8,%9}, {%0,%1,%2,%3};"
        : "+f"(c[0]), "+f"(c[1]), "+f"(c[2]), "+f"(c[3])
        : "r"(a[0]), "r"(a[1]), "r"(a[2]), "r"(a[3]), "r"(b[0]), "r"(b[1]));
}

// ---------------- input projection -> fp16 hi/lo ----------------
__global__ void input_proj_kernel(const float* __restrict__ pose,
                                  const float* __restrict__ Wp,
                                  const float* __restrict__ bp,
                                  __half* __restrict__ xh, __half* __restrict__ xl) {
    long idx = (long)blockIdx.x * blockDim.x + threadIdx.x;
    if (idx >= (long)T_FR * NN * FF) return;
    int f = (int)(idx % FF);
    long tn = idx / FF;
    const float* p = pose + tn * DIN;
    float v = p[0] * Wp[f] + p[1] * Wp[FF + f] + p[2] * Wp[2 * FF + f] + bp[f];
    __half h, l; split_h(v, h, l);
    xh[idx] = h; xl[idx] = l;
}

// ---------------- weight transpose + split ----------------
__global__ void wsplit_kernel(const float* __restrict__ W,
                              __half* __restrict__ hi, __half* __restrict__ lo,
                              int K, int N) {
    __shared__ float tile[32][33];
    int b = blockIdx.z;
    const float* Wb = W + (long)b * K * N;
    __half* hb = hi + (long)b * K * N;
    __half* lb = lo + (long)b * K * N;
    int kb = blockIdx.y * 32, nb = blockIdx.x * 32;
    for (int r = threadIdx.y; r < 32; r += 8)
        tile[r][threadIdx.x] = Wb[(long)(kb + r) * N + nb + threadIdx.x];
    __syncthreads();
    for (int r = threadIdx.y; r < 32; r += 8) {
        float v = tile[threadIdx.x][r];
        __half h, l; split_h(v, h, l);
        long o = (long)(nb + r) * K + kb + threadIdx.x;
        hb[o] = h; lb[o] = l;
    }
}

// ---------------- adjacency -> padded neighbor lists ----------------
__global__ void adjlist_kernel(const int* __restrict__ adj,
                               int* __restrict__ nnz, int* __restrict__ cols) {
    __shared__ int cnt;
    int i = blockIdx.x;
    if (threadIdx.x == 0) cnt = 0;
    __syncthreads();
    for (int j = threadIdx.x; j < NN; j += blockDim.x) {
        if (adj[(long)i * NN + j] > 0) {
            int p = atomicAdd(&cnt, 1);
            if (p < MAXN) cols[i * MAXN + p] = j;
        }
    }
    __syncthreads();
    if (threadIdx.x == 0) nnz[i] = (cnt < MAXN) ? cnt : MAXN;
}

// ============================================================================
// fp16 split-3 tensor-core GEMM, double-buffered cp.async pipeline.
// CTA tile 128x64, warp tile 32x32, BK=32. 2 smem stages.
// Stage layout (halfs): AHI 0, ALO 5120, BHI 10240, BLO 12800; stage=15360.
// ============================================================================
#define AHI 0
#define ALO 5120
#define BHI 10240
#define BLO 12800
#define STG 15360
#define GEMM_SMEM (2 * STG * 2)   // bytes

__global__ __launch_bounds__(256)
void gemm_tc(const __half* __restrict__ Ah, const __half* __restrict__ Al,
             const __half* __restrict__ Bh, const __half* __restrict__ Bl,
             float* __restrict__ C,
             int K, int lda, int ldb, int ldc,
             long aStride, int aDiv, long bStride, int bMod,
             long cOuter, int cDiv, long cInner, int epi) {
    extern __shared__ __align__(16) unsigned short smg[];
    uint32_t sb = smem_u32(smg);

    int tid = threadIdx.x;
    int lane = tid & 31;
    int warp = tid >> 5;
    int wm = warp >> 1;
    int wn = warp & 1;
    int g = lane >> 2;
    int q = lane & 3;

    int b = blockIdx.z;
    int col0 = blockIdx.x * 64;
    int row0 = blockIdx.y * 128;
    const __half* AhB = Ah + (long)(b / aDiv) * aStride;
    const __half* AlB = Al + (long)(b / aDiv) * aStride;
    const __half* BhB = Bh + (long)(b % bMod) * bStride;
    const __half* BlB = Bl + (long)(b % bMod) * bStride;
    float* Cb = C + (long)(b / cDiv) * cOuter + (long)(b % cDiv) * cInner;

    float acc[2][4][4];
    #pragma unroll
    for (int i = 0; i < 2; i++)
        #pragma unroll
        for (int j = 0; j < 4; j++)
            #pragma unroll
            for (int k = 0; k < 4; k++) acc[i][j][k] = 0.f;

    int arow0 = tid >> 2, aseg = tid & 3;
    int brow = tid >> 2, bseg = tid & 3;
    int aRowA = (lane & 15);
    int kHalf = (lane >> 4) << 3;

    // --- pipeline stage issue ---
    auto issue_stage = [&](int k0, int st) {
        uint32_t base = sb + (uint32_t)(st * STG * 2);
        #pragma unroll
        for (int h = 0; h < 2; h++) {
            int row = arow0 + h * 64;
            uint32_t d = base + (uint32_t)((row * 40 + aseg * 8) * 2);
            cp16(d + AHI * 2, AhB + (long)(row0 + row) * lda + k0 + aseg * 8);
            cp16(d + ALO * 2, AlB + (long)(row0 + row) * lda + k0 + aseg * 8);
        }
        {
            uint32_t d = base + (uint32_t)((BHI + brow * 40 + bseg * 8) * 2);
            cp16(d, BhB + (long)(col0 + brow) * ldb + k0 + bseg * 8);
            cp16(d + (BLO - BHI) * 2, BlB + (long)(col0 + brow) * ldb + k0 + bseg * 8);
        }
        asm volatile("cp.async.commit_group;");
    };

    int nIter = K >> 5;
    issue_stage(0, 0);

    for (int i = 0; i < nIter; i++) {
        if (i + 1 < nIter) {
            issue_stage((i + 1) << 5, (i + 1) & 1);
            asm volatile("cp.async.wait_group 1;");
        } else {
            asm volatile("cp.async.wait_group 0;");
        }
        __syncthreads();

        uint32_t stBase = sb + (uint32_t)((i & 1) * STG * 2);
        #pragma unroll
        for (int kk = 0; kk < 32; kk += 16) {
            uint32_t ah[2][4], al[2][4], bhf[4][2], blf[4][2];
            #pragma unroll
            for (int mt = 0; mt < 2; mt++) {
                uint32_t addr = stBase + (uint32_t)(((AHI) + (wm * 32 + mt * 16 + aRowA) * 40 + kk + kHalf) * 2);
                ldsm4(ah[mt], addr);
                ldsm4(al[mt], addr + (ALO - AHI) * 2);
            }
            #pragma unroll
            for (int ng = 0; ng < 2; ng++) {
                uint32_t r[4];
                uint32_t addr = stBase + (uint32_t)(((BHI) + (wn * 32 + ng * 16 + aRowA) * 40 + kk + kHalf) * 2);
                ldsm4(r, addr);
                bhf[ng * 2 + 0][0] = r[0]; bhf[ng * 2 + 0][1] = r[2];
                bhf[ng * 2 + 1][0] = r[1]; bhf[ng * 2 + 1][1] = r[3];
                ldsm4(r, addr + (BLO - BHI) * 2);
                blf[ng * 2 + 0][0] = r[0]; blf[ng * 2 + 0][1] = r[2];
                blf[ng * 2 + 1][0] = r[1]; blf[ng * 2 + 1][1] = r[3];
            }
            #pragma unroll
            for (int mt = 0; mt < 2; mt++)
                #pragma unroll
                for (int nt = 0; nt < 4; nt++) mma_fp16(acc[mt][nt], ah[mt], bhf[nt]);
            #pragma unroll
            for (int mt = 0; mt < 2; mt++)
                #pragma unroll
                for (int nt = 0; nt < 4; nt++) mma_fp16(acc[mt][nt], al[mt], bhf[nt]);
            #pragma unroll
            for (int mt = 0; mt < 2; mt++)
                #pragma unroll
                for (int nt = 0; nt < 4; nt++) mma_fp16(acc[mt][nt], ah[mt], blf[nt]);
        }
        __syncthreads();
    }

    // epilogue
    #pragma unroll
    for (int mt = 0; mt < 2; mt++) {
        #pragma unroll
        for (int nt = 0; nt < 4; nt++) {
            int r = row0 + wm * 32 + mt * 16 + g;
            int c = col0 + wn * 32 + nt * 8 + 2 * q;
            float vv[4] = {acc[mt][nt][0], acc[mt][nt][1], acc[mt][nt][2], acc[mt][nt][3]};
            #pragma unroll
            for (int j = 0; j < 4; j++) {
                float u = vv[j];
                if (epi >= 1) u = (u >= 0.f) ? u : expm1f(u);
                if (epi == 2) u = (u >= 0.f) ? u : expm1f(u);
                vv[j] = u;
            }
            *(float2*)&Cb[(long)r * ldc + c] = make_float2(vv[0], vv[1]);
            *(float2*)&Cb[(long)(r + 8) * ldc + c] = make_float2(vv[2], vv[3]);
        }
    }
}

// ---------------- f/g terms (one warp per row) ----------------
__global__ void fg_kernel(const float* __restrict__ Wh, const float* __restrict__ a,
                          int aMod, float* __restrict__ f, float* __restrict__ g,
                          int batches) {
    long w = ((long)blockIdx.x * blockDim.x + threadIdx.x) >> 5;
    int lane = threadIdx.x & 31;
    if (w >= (long)batches * NN) return;
    int b = (int)(w / NN);
    const float* row = Wh + w * FF;
    const float* ar = a + (long)(b % aMod) * (2 * FF);
    float s1 = 0.f, s2 = 0.f;
    #pragma unroll
    for (int i = 0; i < FF / 32; i++) {
        float v = row[lane + 32 * i];
        s1 += v * ar[lane + 32 * i];
        s2 += v * ar[FF + lane + 32 * i];
    }
    #pragma unroll
    for (int o = 16; o > 0; o >>= 1) {
        s1 += __shfl_down_sync(0xffffffffu, s1, o);
        s2 += __shfl_down_sync(0xffffffffu, s2, o);
    }
    if (lane == 0) { f[w] = s1; g[w] = s2; }
}

// ---------------- sparse softmax over neighbor lists ----------------
__global__ void softmax_sparse_kernel(const float* __restrict__ f, const float* __restrict__ g,
                                      const int* __restrict__ nnz, const int* __restrict__ cols,
                                      float* __restrict__ Pc, int totalRows) {
    int w = (int)(((long)blockIdx.x * blockDim.x + threadIdx.x) >> 5);
    int lane = threadIdx.x & 31;
    if (w >= totalRows) return;
    int b = w >> 9;
    int i = w & 511;
    float fi = f[w];
    const float* gb = g + (long)b * NN;
    int n = nnz[i];
    const int* crow = cols + i * MAXN;
    int nc = (n + 31) >> 5;

    float e[4];
    float mx = -INFINITY;
    for (int c = 0; c < nc; c++) {
        int k = c * 32 + lane;
        float v = -INFINITY;
        if (k < n) {
            float xv = fi + gb[crow[k]];
            v = (xv >= 0.f) ? xv : 0.2f * xv;
        }
        e[c] = v;
        mx = fmaxf(mx, v);
    }
    #pragma unroll
    for (int o = 16; o > 0; o >>= 1) mx = fmaxf(mx, __shfl_xor_sync(0xffffffffu, mx, o));

    float s = 0.f;
    for (int c = 0; c < nc; c++) {
        float ev = (e[c] > -1e30f) ? __expf(e[c] - mx) : 0.f;
        e[c] = ev; s += ev;
    }
    #pragma unroll
    for (int o = 16; o > 0; o >>= 1) s += __shfl_xor_sync(0xffffffffu, s, o);
    float inv = 1.0f / s;

    float* prow = Pc + (long)w * MAXN;
    for (int c = 0; c < nc; c++) {
        int k = c * 32 + lane;
        if (k < n) prow[k] = e[c] * inv;
    }
}

// ---------------- sparse attention apply; writes fp16 hi/lo (+ optional fp32) ----------------
__global__ __launch_bounds__(256)
void spmm_kernel(const float* __restrict__ Pc, const float* __restrict__ Wh,
                 const int* __restrict__ nnz, const int* __restrict__ cols,
                 __half* __restrict__ Chi, __half* __restrict__ Clo,
                 float* __restrict__ Cf, int writeF,
                 long whStride, long cOuter, int cDiv, long cInner, int ldc, int epi) {
    extern __shared__ float WhS[];
    int b = blockIdx.y;
    int c0 = blockIdx.x * 64;
    const float* Whb = Wh + (long)b * whStride;
    long cOff = (long)(b / cDiv) * cOuter + (long)(b % cDiv) * cInner;

    for (int idx = threadIdx.x; idx < NN * 16; idx += 256) {
        int row = idx >> 4;
        int col4 = (idx & 15) << 2;
        *(float4*)&WhS[row * 64 + col4] =
            *(const float4*)&Whb[(long)row * FF + c0 + col4];
    }
    __syncthreads();

    int warp = threadIdx.x >> 5;
    int lane = threadIdx.x & 31;
    for (int i = warp; i < NN; i += 8) {
        int n = nnz[i];
        const int* crow = cols + i * MAXN;
        const float* prow = Pc + ((long)b * NN + i) * MAXN;
        float ax = 0.f, ay = 0.f;
        #pragma unroll 4
        for (int k = 0; k < n; k++) {
            int j = crow[k];
            float wv = prow[k];
            float2 v = *(const float2*)&WhS[j * 64 + 2 * lane];
            ax += wv * v.x; ay += wv * v.y;
        }
        if (epi >= 1) { ax = ax >= 0.f ? ax : expm1f(ax); ay = ay >= 0.f ? ay : expm1f(ay); }
        if (epi == 2) { ax = ax >= 0.f ? ax : expm1f(ax); ay = ay >= 0.f ? ay : expm1f(ay); }
        long o = cOff + (long)i * ldc + c0 + 2 * lane;
        __half hx, lx, hy, ly;
        split_h(ax, hx, lx); split_h(ay, hy, ly);
        __half2 hv; hv.x = hx; hv.y = hy;
        __half2 lv; lv.x = lx; lv.y = ly;
        *(__half2*)&Chi[o] = hv;
        *(__half2*)&Clo[o] = lv;
        if (writeF) *(float2*)&Cf[o] = make_float2(ax, ay);
    }
}

// ---------------- final pool ----------------
__global__ void pool_kernel(const float* __restrict__ x, const float* __restrict__ Wo,
                            const float* __restrict__ bo, float* __restrict__ out) {
    int t = blockIdx.x;
    int f = threadIdx.x;
    __shared__ float m[FF];
    const float* xt = x + (long)t * NN * FF;
    float s = 0.f;
    for (int n = 0; n < NN; n++) s += xt[n * FF + f];
    m[f] = s * (1.0f / NN);
    __syncthreads();
    float o = bo[f];
    for (int k = 0; k < FF; k++) o += m[k] * Wo[k * FF + f];
    out[t * FF + f] = o;
}

// ---------------- host orchestration ----------------
extern "C" void kernel_launch(void* const* d_in, const int* in_sizes, int n_in,
                              void* d_out, int out_size) {
    const float* pose    = (const float*)d_in[0];
    const int*   adj     = (const int*)  d_in[1];
    const float* Wp      = (const float*)d_in[2];
    const float* bp      = (const float*)d_in[3];
    const float* W_heads = (const float*)d_in[4];
    const float* a_heads = (const float*)d_in[5];
    const float* W_out   = (const float*)d_in[6];
    const float* a_out   = (const float*)d_in[7];
    const float* Wo      = (const float*)d_in[8];
    const float* bo      = (const float*)d_in[9];
    float* out = (float*)d_out;

    float *x, *Wh, *fb, *gb, *P;
    __half *xh, *xl, *xch, *xcl, *Wth, *Wtl, *Woth, *Wotl;
    int *nnz, *colsArr;
    cudaGetSymbolAddress((void**)&x,    g_x);
    cudaGetSymbolAddress((void**)&Wh,   g_Wh);
    cudaGetSymbolAddress((void**)&xh,   g_xh);
    cudaGetSymbolAddress((void**)&xl,   g_xl);
    cudaGetSymbolAddress((void**)&xch,  g_xch);
    cudaGetSymbolAddress((void**)&xcl,  g_xcl);
    cudaGetSymbolAddress((void**)&Wth,  g_Wth);
    cudaGetSymbolAddress((void**)&Wtl,  g_Wtl);
    cudaGetSymbolAddress((void**)&Woth, g_Woth);
    cudaGetSymbolAddress((void**)&Wotl, g_Wotl);
    cudaGetSymbolAddress((void**)&fb,   g_f);
    cudaGetSymbolAddress((void**)&gb,   g_g);
    cudaGetSymbolAddress((void**)&P,    g_P);
    cudaGetSymbolAddress((void**)&nnz,  g_nnz);
    cudaGetSymbolAddress((void**)&colsArr, g_cols);

    static bool attrSet = false;
    if (!attrSet) {
        cudaFuncSetAttribute(spmm_kernel,
                             cudaFuncAttributeMaxDynamicSharedMemorySize, NN * 64 * 4);
        cudaFuncSetAttribute(gemm_tc,
                             cudaFuncAttributeMaxDynamicSharedMemorySize, GEMM_SMEM);
        attrSet = true;
    }

    adjlist_kernel<<<NN, 256>>>(adj, nnz, colsArr);

    {
        dim3 blk(32, 8);
        dim3 gh(FF / 32, FF / 32, LL * HH);
        wsplit_kernel<<<gh, blk>>>(W_heads, Wth, Wtl, FF, FF);
        dim3 go(FF / 32, (HH * FF) / 32, LL);
        wsplit_kernel<<<go, blk>>>(W_out, Woth, Wotl, HH * FF, FF);
    }

    {
        long total = (long)T_FR * NN * FF;
        input_proj_kernel<<<(unsigned)((total + 255) / 256), 256>>>(pose, Wp, bp, xh, xl);
    }

    for (int l = 0; l < LL; l++) {
        const __half* Wlh = Wth  + (long)l * HH * FF * FF;
        const __half* Wll = Wtl  + (long)l * HH * FF * FF;
        const __half* Woh = Woth + (long)l * FF * HH * FF;
        const __half* Wol = Wotl + (long)l * FF * HH * FF;
        const float* al  = a_heads + (long)l * HH * 2 * FF;
        const float* aol = a_out   + (long)l * 2 * FF;

        // 2a. Wh[t,h] = x[t] @ W_heads[l,h]
        {
            dim3 grid(FF / 64, NN / 128, T_FR * HH);
            gemm_tc<<<grid, 256, GEMM_SMEM>>>(xh, xl, Wlh, Wll, Wh,
                FF, FF, FF, FF,
                (long)NN * FF, HH,
                (long)FF * FF, HH,
                (long)NN * FF, 1, 0,
                0);
        }
        // 2b. f,g per head
        {
            long warps = (long)T_FR * HH * NN;
            fg_kernel<<<(unsigned)((warps * 32 + 255) / 256), 256>>>(Wh, al, HH, fb, gb, T_FR * HH);
        }
        // 2c. sparse softmax -> compact P
        {
            int rows = T_FR * HH * NN;
            softmax_sparse_kernel<<<(rows * 32 + 255) / 256, 256>>>(fb, gb, nnz, colsArr, P, rows);
        }
        // 2d. xcat = elu(P @ Wh)  -> fp16 hi/lo
        {
            dim3 grid(FF / 64, T_FR * HH);
            spmm_kernel<<<grid, 256, NN * 64 * 4>>>(P, Wh, nnz, colsArr,
                xch, xcl, (float*)0, 0,
                (long)NN * FF,
                (long)NN * HH * FF, HH, FF, HH * FF, 1);
        }
        // 2e. Whout[t] = xcat[t] @ W_out[l]
        {
            dim3 grid(FF / 64, NN / 128, T_FR);
            gemm_tc<<<grid, 256, GEMM_SMEM>>>(xch, xcl, Woh, Wol, Wh,
                HH * FF, HH * FF, HH * FF, FF,
                (long)NN * HH * FF, 1,
                0, 1,
                (long)NN * FF, 1, 0,
                0);
        }
        // 2f. f,g for out-head
        {
            long warps = (long)T_FR * NN;
            fg_kernel<<<(unsigned)((warps * 32 + 255) / 256), 256>>>(Wh, aol, 1, fb, gb, T_FR);
        }
        // 2g. sparse softmax -> compact P
        {
            int rows = T_FR * NN;
            softmax_sparse_kernel<<<(rows * 32 + 255) / 256, 256>>>(fb, gb, nnz, colsArr, P, rows);
        }
        // 2h. x = elu(elu(P @ Whout))  -> fp32 + fp16 hi/lo
        {
            dim3 grid(FF / 64, T_FR);
            spmm_kernel<<<grid, 256, NN * 64 * 4>>>(P, Wh, nnz, colsArr,
                xh, xl, x, 1,
                (long)NN * FF,
                (long)NN * FF, 1, 0, FF, 2);
        }
    }

    pool_kernel<<<T_FR, 256>>>(x, Wo, bo, out);
}

// round 7
// speedup vs baseline: 1.6893x; 1.0911x over previous
#include <cuda_runtime.h>
#include <cuda_fp16.h>
#include <math.h>
#include <stdint.h>

// Problem constants
#define T_FR 32
#define NN 512
#define FF 256
#define HH 8
#define LL 3
#define DIN 3
#define MAXN 128

// ---------------- scratch (device globals; allocation-free rule) ----------------
__device__ float  g_x[T_FR * NN * FF];
__device__ float  g_Wh[T_FR * HH * NN * FF];
__device__ __half g_xh[T_FR * NN * FF];
__device__ __half g_xl[T_FR * NN * FF];
__device__ __half g_xch[T_FR * NN * HH * FF];
__device__ __half g_xcl[T_FR * NN * HH * FF];
__device__ __half g_Wth[LL * HH * FF * FF];     // W_heads^T hi  [l][h][n][k]
__device__ __half g_Woth[LL * FF * HH * FF];    // W_out^T hi    [l][n=256][k=2048]
__device__ float  g_f[T_FR * HH * NN];
__device__ float  g_g[T_FR * HH * NN];
__device__ float  g_P[(long)T_FR * HH * NN * MAXN];
__device__ int    g_nnz[NN];
__device__ int    g_cols[NN * MAXN];

// ---------------- helpers ----------------
__device__ __forceinline__ void split_h(float x, __half& h, __half& l) {
    h = __float2half_rn(x);
    l = __float2half_rn(x - __half2float(h));
}
__device__ __forceinline__ uint32_t smem_u32(const void* p) {
    uint32_t a;
    asm("{ .reg .u64 t; cvta.to.shared.u64 t, %1; cvt.u32.u64 %0, t; }" : "=r"(a) : "l"(p));
    return a;
}
__device__ __forceinline__ void cp16(uint32_t dst, const void* src) {
    asm volatile("cp.async.cg.shared.global [%0], [%1], 16;" :: "r"(dst), "l"(src));
}
__device__ __forceinline__ void ldsm4(uint32_t* r, uint32_t addr) {
    asm volatile("ldmatrix.sync.aligned.m8n8.x4.shared.b16 {%0,%1,%2,%3}, [%4];"
        : "=r"(r[0]), "=r"(r[1]), "=r"(r[2]), "=r"(r[3]) : "r"(addr));
}
__device__ __forceinline__ void mma_fp16(float* c, const uint32_t* a, const uint32_t* b) {
    asm volatile("mma.sync.aligned.m16n8k16.row.col.f32.f16.f16.f32 "
        "{%0,%1,%2,%3}, {%4,%5,%6,%7}, {%8,%9}, {%0,%1,%2,%3};"
        : "+f"(c[0]), "+f"(c[1]), "+f"(c[2]), "+f"(c[3])
        : "r"(a[0]), "r"(a[1]), "r"(a[2]), "r"(a[3]), "r"(b[0]), "r"(b[1]));
}

// ---------------- input projection -> fp16 hi/lo ----------------
__global__ void input_proj_kernel(const float* __restrict__ pose,
                                  const float* __restrict__ Wp,
                                  const float* __restrict__ bp,
                                  __half* __restrict__ xh, __half* __restrict__ xl) {
    long idx = (long)blockIdx.x * blockDim.x + threadIdx.x;
    if (idx >= (long)T_FR * NN * FF) return;
    int f = (int)(idx % FF);
    long tn = idx / FF;
    const float* p = pose + tn * DIN;
    float v = p[0] * Wp[f] + p[1] * Wp[FF + f] + p[2] * Wp[2 * FF + f] + bp[f];
    __half h, l; split_h(v, h, l);
    xh[idx] = h; xl[idx] = l;
}

// ---------------- weight transpose: W [K][N] fp32 -> Wt hi [N][K] fp16 ----------------
__global__ void wsplit_kernel(const float* __restrict__ W,
                              __half* __restrict__ hi, int K, int N) {
    __shared__ float tile[32][33];
    int b = blockIdx.z;
    const float* Wb = W + (long)b * K * N;
    __half* hb = hi + (long)b * K * N;
    int kb = blockIdx.y * 32, nb = blockIdx.x * 32;
    for (int r = threadIdx.y; r < 32; r += 8)
        tile[r][threadIdx.x] = Wb[(long)(kb + r) * N + nb + threadIdx.x];
    __syncthreads();
    for (int r = threadIdx.y; r < 32; r += 8) {
        float v = tile[threadIdx.x][r];
        long o = (long)(nb + r) * K + kb + threadIdx.x;
        hb[o] = __float2half_rn(v);
    }
}

// ---------------- adjacency -> padded neighbor lists ----------------
__global__ void adjlist_kernel(const int* __restrict__ adj,
                               int* __restrict__ nnz, int* __restrict__ cols) {
    __shared__ int cnt;
    int i = blockIdx.x;
    if (threadIdx.x == 0) cnt = 0;
    __syncthreads();
    for (int j = threadIdx.x; j < NN; j += blockDim.x) {
        if (adj[(long)i * NN + j] > 0) {
            int p = atomicAdd(&cnt, 1);
            if (p < MAXN) cols[i * MAXN + p] = j;
        }
    }
    __syncthreads();
    if (threadIdx.x == 0) nnz[i] = (cnt < MAXN) ? cnt : MAXN;
}

// ============================================================================
// fp16 2-pass tensor-core GEMM: C = (Ahi + Alo) @ Bh^T.
// CTA tile 128x128, warp tile 32x64 (8 warps = 4m x 2n), BK=32, 2-stage cp.async.
// smem stage layout (halfs): AHI 0, ALO 5120, BHI 10240; stage = 15360 halfs.
// ============================================================================
#define AHI 0
#define ALO 5120
#define BHI 10240
#define STG 15360
#define GEMM_SMEM (2 * STG * 2)   // 61440 bytes

__global__ __launch_bounds__(256)
void gemm_tc(const __half* __restrict__ Ah, const __half* __restrict__ Al,
             const __half* __restrict__ Bh,
             float* __restrict__ C,
             int K, int lda, int ldb, int ldc,
             long aStride, int aDiv, long bStride, int bMod,
             long cOuter, int cDiv, long cInner, int epi) {
    extern __shared__ __align__(16) unsigned short smg[];
    uint32_t sb = smem_u32(smg);

    int tid = threadIdx.x;
    int lane = tid & 31;
    int warp = tid >> 5;
    int wm = warp >> 1;        // 0..3 -> rows wm*32
    int wn = warp & 1;         // 0..1 -> cols wn*64
    int g = lane >> 2;
    int q = lane & 3;

    int b = blockIdx.z;
    int col0 = blockIdx.x * 128;
    int row0 = blockIdx.y * 128;
    const __half* AhB = Ah + (long)(b / aDiv) * aStride;
    const __half* AlB = Al + (long)(b / aDiv) * aStride;
    const __half* BhB = Bh + (long)(b % bMod) * bStride;
    float* Cb = C + (long)(b / cDiv) * cOuter + (long)(b % cDiv) * cInner;

    float acc[2][8][4];
    #pragma unroll
    for (int i = 0; i < 2; i++)
        #pragma unroll
        for (int j = 0; j < 8; j++)
            #pragma unroll
            for (int k = 0; k < 4; k++) acc[i][j][k] = 0.f;

    int arow0 = tid >> 2, aseg = tid & 3;     // rows 0..63 (+64), segs of 8 halves
    int aRowA = (lane & 15);
    int kHalf = (lane >> 4) << 3;

    auto issue_stage = [&](int k0, int st) {
        uint32_t base = sb + (uint32_t)(st * STG * 2);
        #pragma unroll
        for (int h = 0; h < 2; h++) {
            int row = arow0 + h * 64;
            uint32_t d = base + (uint32_t)((row * 40 + aseg * 8) * 2);
            cp16(d + AHI * 2, AhB + (long)(row0 + row) * lda + k0 + aseg * 8);
            cp16(d + ALO * 2, AlB + (long)(row0 + row) * lda + k0 + aseg * 8);
            cp16(d + BHI * 2, BhB + (long)(col0 + row) * ldb + k0 + aseg * 8);
        }
        asm volatile("cp.async.commit_group;");
    };

    int nIter = K >> 5;
    issue_stage(0, 0);

    for (int i = 0; i < nIter; i++) {
        if (i + 1 < nIter) {
            issue_stage((i + 1) << 5, (i + 1) & 1);
            asm volatile("cp.async.wait_group 1;");
        } else {
            asm volatile("cp.async.wait_group 0;");
        }
        __syncthreads();

        uint32_t stBase = sb + (uint32_t)((i & 1) * STG * 2);
        #pragma unroll
        for (int kk = 0; kk < 32; kk += 16) {
            uint32_t ah[2][4], al[2][4], bf[8][2];
            #pragma unroll
            for (int mt = 0; mt < 2; mt++) {
                uint32_t addr = stBase + (uint32_t)(((AHI) + (wm * 32 + mt * 16 + aRowA) * 40 + kk + kHalf) * 2);
                ldsm4(ah[mt], addr);
                ldsm4(al[mt], addr + (ALO - AHI) * 2);
            }
            #pragma unroll
            for (int ng = 0; ng < 4; ng++) {
                uint32_t r[4];
                uint32_t addr = stBase + (uint32_t)(((BHI) + (wn * 64 + ng * 16 + aRowA) * 40 + kk + kHalf) * 2);
                ldsm4(r, addr);
                bf[ng * 2 + 0][0] = r[0]; bf[ng * 2 + 0][1] = r[2];
                bf[ng * 2 + 1][0] = r[1]; bf[ng * 2 + 1][1] = r[3];
            }
            #pragma unroll
            for (int mt = 0; mt < 2; mt++)
                #pragma unroll
                for (int nt = 0; nt < 8; nt++) mma_fp16(acc[mt][nt], ah[mt], bf[nt]);
            #pragma unroll
            for (int mt = 0; mt < 2; mt++)
                #pragma unroll
                for (int nt = 0; nt < 8; nt++) mma_fp16(acc[mt][nt], al[mt], bf[nt]);
        }
        __syncthreads();
    }

    // epilogue
    #pragma unroll
    for (int mt = 0; mt < 2; mt++) {
        #pragma unroll
        for (int nt = 0; nt < 8; nt++) {
            int r = row0 + wm * 32 + mt * 16 + g;
            int c = col0 + wn * 64 + nt * 8 + 2 * q;
            float vv[4] = {acc[mt][nt][0], acc[mt][nt][1], acc[mt][nt][2], acc[mt][nt][3]};
            #pragma unroll
            for (int j = 0; j < 4; j++) {
                float u = vv[j];
                if (epi >= 1) u = (u >= 0.f) ? u : expm1f(u);
                if (epi == 2) u = (u >= 0.f) ? u : expm1f(u);
                vv[j] = u;
            }
            *(float2*)&Cb[(long)r * ldc + c] = make_float2(vv[0], vv[1]);
            *(float2*)&Cb[(long)(r + 8) * ldc + c] = make_float2(vv[2], vv[3]);
        }
    }
}

// ---------------- f/g terms (one warp per row) ----------------
__global__ void fg_kernel(const float* __restrict__ Wh, const float* __restrict__ a,
                          int aMod, float* __restrict__ f, float* __restrict__ g,
                          int batches) {
    long w = ((long)blockIdx.x * blockDim.x + threadIdx.x) >> 5;
    int lane = threadIdx.x & 31;
    if (w >= (long)batches * NN) return;
    int b = (int)(w / NN);
    const float* row = Wh + w * FF;
    const float* ar = a + (long)(b % aMod) * (2 * FF);
    float s1 = 0.f, s2 = 0.f;
    #pragma unroll
    for (int i = 0; i < FF / 32; i++) {
        float v = row[lane + 32 * i];
        s1 += v * ar[lane + 32 * i];
        s2 += v * ar[FF + lane + 32 * i];
    }
    #pragma unroll
    for (int o = 16; o > 0; o >>= 1) {
        s1 += __shfl_down_sync(0xffffffffu, s1, o);
        s2 += __shfl_down_sync(0xffffffffu, s2, o);
    }
    if (lane == 0) { f[w] = s1; g[w] = s2; }
}

// ---------------- sparse softmax over neighbor lists ----------------
__global__ void softmax_sparse_kernel(const float* __restrict__ f, const float* __restrict__ g,
                                      const int* __restrict__ nnz, const int* __restrict__ cols,
                                      float* __restrict__ Pc, int totalRows) {
    int w = (int)(((long)blockIdx.x * blockDim.x + threadIdx.x) >> 5);
    int lane = threadIdx.x & 31;
    if (w >= totalRows) return;
    int b = w >> 9;
    int i = w & 511;
    float fi = f[w];
    const float* gb = g + (long)b * NN;
    int n = nnz[i];
    const int* crow = cols + i * MAXN;
    int nc = (n + 31) >> 5;

    float e[4];
    float mx = -INFINITY;
    for (int c = 0; c < nc; c++) {
        int k = c * 32 + lane;
        float v = -INFINITY;
        if (k < n) {
            float xv = fi + gb[crow[k]];
            v = (xv >= 0.f) ? xv : 0.2f * xv;
        }
        e[c] = v;
        mx = fmaxf(mx, v);
    }
    #pragma unroll
    for (int o = 16; o > 0; o >>= 1) mx = fmaxf(mx, __shfl_xor_sync(0xffffffffu, mx, o));

    float s = 0.f;
    for (int c = 0; c < nc; c++) {
        float ev = (e[c] > -1e30f) ? __expf(e[c] - mx) : 0.f;
        e[c] = ev; s += ev;
    }
    #pragma unroll
    for (int o = 16; o > 0; o >>= 1) s += __shfl_xor_sync(0xffffffffu, s, o);
    float inv = 1.0f / s;

    float* prow = Pc + (long)w * MAXN;
    for (int c = 0; c < nc; c++) {
        int k = c * 32 + lane;
        if (k < n) prow[k] = e[c] * inv;
    }
}

// ---------------- sparse attention apply; writes fp16 hi/lo (+ optional fp32) ----------------
__global__ __launch_bounds__(256)
void spmm_kernel(const float* __restrict__ Pc, const float* __restrict__ Wh,
                 const int* __restrict__ nnz, const int* __restrict__ cols,
                 __half* __restrict__ Chi, __half* __restrict__ Clo,
                 float* __restrict__ Cf, int writeF,
                 long whStride, long cOuter, int cDiv, long cInner, int ldc, int epi) {
    extern __shared__ float WhS[];
    int b = blockIdx.y;
    int c0 = blockIdx.x * 64;
    const float* Whb = Wh + (long)b * whStride;
    long cOff = (long)(b / cDiv) * cOuter + (long)(b % cDiv) * cInner;

    for (int idx = threadIdx.x; idx < NN * 16; idx += 256) {
        int row = idx >> 4;
        int col4 = (idx & 15) << 2;
        *(float4*)&WhS[row * 64 + col4] =
            *(const float4*)&Whb[(long)row * FF + c0 + col4];
    }
    __syncthreads();

    int warp = threadIdx.x >> 5;
    int lane = threadIdx.x & 31;
    for (int i = warp; i < NN; i += 8) {
        int n = nnz[i];
        const int* crow = cols + i * MAXN;
        const float* prow = Pc + ((long)b * NN + i) * MAXN;
        float ax = 0.f, ay = 0.f;
        #pragma unroll 4
        for (int k = 0; k < n; k++) {
            int j = crow[k];
            float wv = prow[k];
            float2 v = *(const float2*)&WhS[j * 64 + 2 * lane];
            ax += wv * v.x; ay += wv * v.y;
        }
        if (epi >= 1) { ax = ax >= 0.f ? ax : expm1f(ax); ay = ay >= 0.f ? ay : expm1f(ay); }
        if (epi == 2) { ax = ax >= 0.f ? ax : expm1f(ax); ay = ay >= 0.f ? ay : expm1f(ay); }
        long o = cOff + (long)i * ldc + c0 + 2 * lane;
        __half hx, lx, hy, ly;
        split_h(ax, hx, lx); split_h(ay, hy, ly);
        __half2 hv; hv.x = hx; hv.y = hy;
        __half2 lv; lv.x = lx; lv.y = ly;
        *(__half2*)&Chi[o] = hv;
        *(__half2*)&Clo[o] = lv;
        if (writeF) *(float2*)&Cf[o] = make_float2(ax, ay);
    }
}

// ---------------- final pool ----------------
__global__ void pool_kernel(const float* __restrict__ x, const float* __restrict__ Wo,
                            const float* __restrict__ bo, float* __restrict__ out) {
    int t = blockIdx.x;
    int f = threadIdx.x;
    __shared__ float m[FF];
    const float* xt = x + (long)t * NN * FF;
    float s = 0.f;
    for (int n = 0; n < NN; n++) s += xt[n * FF + f];
    m[f] = s * (1.0f / NN);
    __syncthreads();
    float o = bo[f];
    for (int k = 0; k < FF; k++) o += m[k] * Wo[k * FF + f];
    out[t * FF + f] = o;
}

// ---------------- host orchestration ----------------
extern "C" void kernel_launch(void* const* d_in, const int* in_sizes, int n_in,
                              void* d_out, int out_size) {
    const float* pose    = (const float*)d_in[0];
    const int*   adj     = (const int*)  d_in[1];
    const float* Wp      = (const float*)d_in[2];
    const float* bp      = (const float*)d_in[3];
    const float* W_heads = (const float*)d_in[4];
    const float* a_heads = (const float*)d_in[5];
    const float* W_out   = (const float*)d_in[6];
    const float* a_out   = (const float*)d_in[7];
    const float* Wo      = (const float*)d_in[8];
    const float* bo      = (const float*)d_in[9];
    float* out = (float*)d_out;

    float *x, *Wh, *fb, *gb, *P;
    __half *xh, *xl, *xch, *xcl, *Wth, *Woth;
    int *nnz, *colsArr;
    cudaGetSymbolAddress((void**)&x,    g_x);
    cudaGetSymbolAddress((void**)&Wh,   g_Wh);
    cudaGetSymbolAddress((void**)&xh,   g_xh);
    cudaGetSymbolAddress((void**)&xl,   g_xl);
    cudaGetSymbolAddress((void**)&xch,  g_xch);
    cudaGetSymbolAddress((void**)&xcl,  g_xcl);
    cudaGetSymbolAddress((void**)&Wth,  g_Wth);
    cudaGetSymbolAddress((void**)&Woth, g_Woth);
    cudaGetSymbolAddress((void**)&fb,   g_f);
    cudaGetSymbolAddress((void**)&gb,   g_g);
    cudaGetSymbolAddress((void**)&P,    g_P);
    cudaGetSymbolAddress((void**)&nnz,  g_nnz);
    cudaGetSymbolAddress((void**)&colsArr, g_cols);

    static bool attrSet = false;
    if (!attrSet) {
        cudaFuncSetAttribute(spmm_kernel,
                             cudaFuncAttributeMaxDynamicSharedMemorySize, NN * 64 * 4);
        cudaFuncSetAttribute(gemm_tc,
                             cudaFuncAttributeMaxDynamicSharedMemorySize, GEMM_SMEM);
        attrSet = true;
    }

    adjlist_kernel<<<NN, 256>>>(adj, nnz, colsArr);

    {
        dim3 blk(32, 8);
        dim3 gh(FF / 32, FF / 32, LL * HH);
        wsplit_kernel<<<gh, blk>>>(W_heads, Wth, FF, FF);
        dim3 go(FF / 32, (HH * FF) / 32, LL);
        wsplit_kernel<<<go, blk>>>(W_out, Woth, HH * FF, FF);
    }

    {
        long total = (long)T_FR * NN * FF;
        input_proj_kernel<<<(unsigned)((total + 255) / 256), 256>>>(pose, Wp, bp, xh, xl);
    }

    for (int l = 0; l < LL; l++) {
        const __half* Wlh = Wth  + (long)l * HH * FF * FF;
        const __half* Woh = Woth + (long)l * FF * HH * FF;
        const float* al  = a_heads + (long)l * HH * 2 * FF;
        const float* aol = a_out   + (long)l * 2 * FF;

        // 2a. Wh[t,h] = x[t] @ W_heads[l,h]   (2-pass fp16, K=256)
        {
            dim3 grid(FF / 128, NN / 128, T_FR * HH);
            gemm_tc<<<grid, 256, GEMM_SMEM>>>(xh, xl, Wlh, Wh,
                FF, FF, FF, FF,
                (long)NN * FF, HH,
                (long)FF * FF, HH,
                (long)NN * FF, 1, 0,
                0);
        }
        // 2b. f,g per head
        {
            long warps = (long)T_FR * HH * NN;
            fg_kernel<<<(unsigned)((warps * 32 + 255) / 256), 256>>>(Wh, al, HH, fb, gb, T_FR * HH);
        }
        // 2c. sparse softmax -> compact P
        {
            int rows = T_FR * HH * NN;
            softmax_sparse_kernel<<<(rows * 32 + 255) / 256, 256>>>(fb, gb, nnz, colsArr, P, rows);
        }
        // 2d. xcat = elu(P @ Wh)  -> fp16 hi/lo
        {
            dim3 grid(FF / 64, T_FR * HH);
            spmm_kernel<<<grid, 256, NN * 64 * 4>>>(P, Wh, nnz, colsArr,
                xch, xcl, (float*)0, 0,
                (long)NN * FF,
                (long)NN * HH * FF, HH, FF, HH * FF, 1);
        }
        // 2e. Whout[t] = xcat[t] @ W_out[l]  (2-pass fp16, K=2048)
        {
            dim3 grid(FF / 128, NN / 128, T_FR);
            gemm_tc<<<grid, 256, GEMM_SMEM>>>(xch, xcl, Woh, Wh,
                HH * FF, HH * FF, HH * FF, FF,
                (long)NN * HH * FF, 1,
                0, 1,
                (long)NN * FF, 1, 0,
                0);
        }
        // 2f. f,g for out-head
        {
            long warps = (long)T_FR * NN;
            fg_kernel<<<(unsigned)((warps * 32 + 255) / 256), 256>>>(Wh, aol, 1, fb, gb, T_FR);
        }
        // 2g. sparse softmax -> compact P
        {
            int rows = T_FR * NN;
            softmax_sparse_kernel<<<(rows * 32 + 255) / 256, 256>>>(fb, gb, nnz, colsArr, P, rows);
        }
        // 2h. x = elu(elu(P @ Whout))  -> fp32 + fp16 hi/lo
        {
            dim3 grid(FF / 64, T_FR);
            spmm_kernel<<<grid, 256, NN * 64 * 4>>>(P, Wh, nnz, colsArr,
                xh, xl, x, 1,
                (long)NN * FF,
                (long)NN * FF, 1, 0, FF, 2);
        }
    }

    pool_kernel<<<T_FR, 256>>>(x, Wo, bo, out);
}

// round 9
// speedup vs baseline: 2.2469x; 1.3300x over previous
#include <cuda_runtime.h>
#include <cuda_fp16.h>
#include <math.h>
#include <stdint.h>

// Problem constants
#define T_FR 32
#define NN 512
#define FF 256
#define HH 8
#define LL 3
#define DIN 3
#define MAXN 128
#define SCH 32   // spmm column chunk

// ---------------- scratch (device globals; allocation-free rule) ----------------
__device__ float  g_x[T_FR * NN * FF];
__device__ float  g_Wh[T_FR * HH * NN * FF];
__device__ __half g_xh[T_FR * NN * FF];
__device__ __half g_xl[T_FR * NN * FF];
__device__ __half g_xch[T_FR * NN * HH * FF];
__device__ __half g_xcl[T_FR * NN * HH * FF];
__device__ __half g_Wth[LL * HH * FF * FF];     // W_heads^T [l][h][n][k] fp16
__device__ __half g_Woth[LL * FF * HH * FF];    // W_out^T   [l][n][k]    fp16
__device__ float  g_f[T_FR * HH * NN];
__device__ float  g_g[T_FR * HH * NN];
__device__ float  g_P[(long)T_FR * HH * NN * MAXN];
__device__ int    g_nnz[NN];
__device__ int    g_cols[NN * MAXN];

// ---------------- helpers ----------------
__device__ __forceinline__ void split_h(float x, __half& h, __half& l) {
    h = __float2half_rn(x);
    l = __float2half_rn(x - __half2float(h));
}
__device__ __forceinline__ uint32_t smem_u32(const void* p) {
    uint32_t a;
    asm("{ .reg .u64 t; cvta.to.shared.u64 t, %1; cvt.u32.u64 %0, t; }" : "=r"(a) : "l"(p));
    return a;
}
__device__ __forceinline__ void cp16(uint32_t dst, const void* src) {
    asm volatile("cp.async.cg.shared.global [%0], [%1], 16;" :: "r"(dst), "l"(src));
}
__device__ __forceinline__ void ldsm4(uint32_t* r, uint32_t addr) {
    asm volatile("ldmatrix.sync.aligned.m8n8.x4.shared.b16 {%0,%1,%2,%3}, [%4];"
        : "=r"(r[0]), "=r"(r[1]), "=r"(r[2]), "=r"(r[3]) : "r"(addr));
}
__device__ __forceinline__ void mma_fp16(float* c, const uint32_t* a, const uint32_t* b) {
    asm volatile("mma.sync.aligned.m16n8k16.row.col.f32.f16.f16.f32 "
        "{%0,%1,%2,%3}, {%4,%5,%6,%7}, {%8,%9}, {%0,%1,%2,%3};"
        : "+f"(c[0]), "+f"(c[1]), "+f"(c[2]), "+f"(c[3])
        : "r"(a[0]), "r"(a[1]), "r"(a[2]), "r"(a[3]), "r"(b[0]), "r"(b[1]));
}

// ---------------- input projection -> fp16 hi/lo ----------------
__global__ void input_proj_kernel(const float* __restrict__ pose,
                                  const float* __restrict__ Wp,
                                  const float* __restrict__ bp,
                                  __half* __restrict__ xh, __half* __restrict__ xl) {
    long idx = (long)blockIdx.x * blockDim.x + threadIdx.x;
    if (idx >= (long)T_FR * NN * FF) return;
    int f = (int)(idx % FF);
    long tn = idx / FF;
    const float* p = pose + tn * DIN;
    float v = p[0] * Wp[f] + p[1] * Wp[FF + f] + p[2] * Wp[2 * FF + f] + bp[f];
    __half h, l; split_h(v, h, l);
    xh[idx] = h; xl[idx] = l;
}

// ---------------- weight transpose: W [K][N] fp32 -> Wt [N][K] fp16 ----------------
__global__ void wsplit_kernel(const float* __restrict__ W,
                              __half* __restrict__ hi, int K, int N) {
    __shared__ float tile[32][33];
    int b = blockIdx.z;
    const float* Wb = W + (long)b * K * N;
    __half* hb = hi + (long)b * K * N;
    int kb = blockIdx.y * 32, nb = blockIdx.x * 32;
    for (int r = threadIdx.y; r < 32; r += 8)
        tile[r][threadIdx.x] = Wb[(long)(kb + r) * N + nb + threadIdx.x];
    __syncthreads();
    for (int r = threadIdx.y; r < 32; r += 8) {
        float v = tile[threadIdx.x][r];
        long o = (long)(nb + r) * K + kb + threadIdx.x;
        hb[o] = __float2half_rn(v);
    }
}

// ---------------- adjacency -> padded neighbor lists ----------------
__global__ void adjlist_kernel(const int* __restrict__ adj,
                               int* __restrict__ nnz, int* __restrict__ cols) {
    __shared__ int cnt;
    int i = blockIdx.x;
    if (threadIdx.x == 0) cnt = 0;
    __syncthreads();
    for (int j = threadIdx.x; j < NN; j += blockDim.x) {
        if (adj[(long)i * NN + j] > 0) {
            int p = atomicAdd(&cnt, 1);
            if (p < MAXN) cols[i * MAXN + p] = j;
        }
    }
    __syncthreads();
    if (threadIdx.x == 0) nnz[i] = (cnt < MAXN) ? cnt : MAXN;
}

// ---------------- zero f/g accumulators ----------------
__global__ void zero_fg_kernel(float* __restrict__ f, float* __restrict__ g) {
    int i = blockIdx.x * blockDim.x + threadIdx.x;
    if (i < T_FR * HH * NN) { f[i] = 0.f; g[i] = 0.f; }
}

// ============================================================================
// fp16 2-pass tensor-core GEMM: C = (Ahi + Alo) @ Bh^T, fused f/g epilogue.
// CTA tile 128x128, warp 32x64, BK=32, 3-stage cp.async, 1 sync/iter.
// ============================================================================
#define AHI 0
#define ALO 5120
#define BHI 10240
#define STG 15360
#define GEMM_SMEM (3 * STG * 2)   // 92160 bytes

__global__ __launch_bounds__(256)
void gemm_tc(const __half* __restrict__ Ah, const __half* __restrict__ Al,
             const __half* __restrict__ Bh,
             float* __restrict__ C,
             int K, int lda, int ldb, int ldc,
             long aStride, int aDiv, long bStride, int bMod,
             long cOuter, int cDiv, long cInner, int epi,
             float* __restrict__ fOut, float* __restrict__ gOut,
             const float* __restrict__ aVec, int aMod, int fgEnable) {
    extern __shared__ __align__(16) unsigned short smg[];
    uint32_t sb = smem_u32(smg);

    int tid = threadIdx.x;
    int lane = tid & 31;
    int warp = tid >> 5;
    int wm = warp >> 1;
    int wn = warp & 1;
    int g = lane >> 2;
    int q = lane & 3;

    int b = blockIdx.z;
    int col0 = blockIdx.x * 128;
    int row0 = blockIdx.y * 128;
    const __half* AhB = Ah + (long)(b / aDiv) * aStride;
    const __half* AlB = Al + (long)(b / aDiv) * aStride;
    const __half* BhB = Bh + (long)(b % bMod) * bStride;
    float* Cb = C + (long)(b / cDiv) * cOuter + (long)(b % cDiv) * cInner;

    float acc[2][8][4];
    #pragma unroll
    for (int i = 0; i < 2; i++)
        #pragma unroll
        for (int j = 0; j < 8; j++)
            #pragma unroll
            for (int k = 0; k < 4; k++) acc[i][j][k] = 0.f;

    int arow0 = tid >> 2, aseg = tid & 3;
    int aRowA = (lane & 15);
    int kHalf = (lane >> 4) << 3;

    auto issue_stage = [&](int k0, int st) {
        uint32_t base = sb + (uint32_t)(st * STG * 2);
        #pragma unroll
        for (int h = 0; h < 2; h++) {
            int row = arow0 + h * 64;
            uint32_t d = base + (uint32_t)((row * 40 + aseg * 8) * 2);
            cp16(d + AHI * 2, AhB + (long)(row0 + row) * lda + k0 + aseg * 8);
            cp16(d + ALO * 2, AlB + (long)(row0 + row) * lda + k0 + aseg * 8);
            cp16(d + BHI * 2, BhB + (long)(col0 + row) * ldb + k0 + aseg * 8);
        }
        asm volatile("cp.async.commit_group;");
    };

    int nIter = K >> 5;
    issue_stage(0, 0);
    issue_stage(32, 1);

    int slot = 0;
    for (int i = 0; i < nIter; i++) {
        if (i < nIter - 1) {
            asm volatile("cp.async.wait_group 1;");
        } else {
            asm volatile("cp.async.wait_group 0;");
        }
        __syncthreads();
        if (i + 2 < nIter) {
            int ws = slot + 2; if (ws >= 3) ws -= 3;
            issue_stage((i + 2) << 5, ws);
        }

        uint32_t stBase = sb + (uint32_t)(slot * STG * 2);
        #pragma unroll
        for (int kk = 0; kk < 32; kk += 16) {
            uint32_t ah[2][4], al[2][4], bf[8][2];
            #pragma unroll
            for (int mt = 0; mt < 2; mt++) {
                uint32_t addr = stBase + (uint32_t)(((AHI) + (wm * 32 + mt * 16 + aRowA) * 40 + kk + kHalf) * 2);
                ldsm4(ah[mt], addr);
                ldsm4(al[mt], addr + (ALO - AHI) * 2);
            }
            #pragma unroll
            for (int ng = 0; ng < 4; ng++) {
                uint32_t r[4];
                uint32_t addr = stBase + (uint32_t)(((BHI) + (wn * 64 + ng * 16 + aRowA) * 40 + kk + kHalf) * 2);
                ldsm4(r, addr);
                bf[ng * 2 + 0][0] = r[0]; bf[ng * 2 + 0][1] = r[2];
                bf[ng * 2 + 1][0] = r[1]; bf[ng * 2 + 1][1] = r[3];
            }
            #pragma unroll
            for (int mt = 0; mt < 2; mt++)
                #pragma unroll
                for (int nt = 0; nt < 8; nt++) mma_fp16(acc[mt][nt], ah[mt], bf[nt]);
            #pragma unroll
            for (int mt = 0; mt < 2; mt++)
                #pragma unroll
                for (int nt = 0; nt < 8; nt++) mma_fp16(acc[mt][nt], al[mt], bf[nt]);
        }
        slot++; if (slot >= 3) slot = 0;
    }

    // ---- epilogue: store C (+epi), fused f/g partial dots ----
    float facc[4] = {0.f, 0.f, 0.f, 0.f};
    float gacc[4] = {0.f, 0.f, 0.f, 0.f};
    const float* av = fgEnable ? (aVec + (long)(b % aMod) * (2 * FF)) : (const float*)0;

    #pragma unroll
    for (int mt = 0; mt < 2; mt++) {
        #pragma unroll
        for (int nt = 0; nt < 8; nt++) {
            int r = row0 + wm * 32 + mt * 16 + g;
            int c = col0 + wn * 64 + nt * 8 + 2 * q;
            float v0 = acc[mt][nt][0], v1 = acc[mt][nt][1];
            float v2 = acc[mt][nt][2], v3 = acc[mt][nt][3];
            if (fgEnable) {
                float a10 = av[c], a11 = av[c + 1];
                float a20 = av[FF + c], a21 = av[FF + c + 1];
                facc[mt * 2 + 0] += v0 * a10 + v1 * a11;
                gacc[mt * 2 + 0] += v0 * a20 + v1 * a21;
                facc[mt * 2 + 1] += v2 * a10 + v3 * a11;
                gacc[mt * 2 + 1] += v2 * a20 + v3 * a21;
            }
            float vv[4] = {v0, v1, v2, v3};
            #pragma unroll
            for (int j = 0; j < 4; j++) {
                float u = vv[j];
                if (epi >= 1) u = (u >= 0.f) ? u : expm1f(u);
                if (epi == 2) u = (u >= 0.f) ? u : expm1f(u);
                vv[j] = u;
            }
            *(float2*)&Cb[(long)r * ldc + c] = make_float2(vv[0], vv[1]);
            *(float2*)&Cb[(long)(r + 8) * ldc + c] = make_float2(vv[2], vv[3]);
        }
    }
    if (fgEnable) {
        #pragma unroll
        for (int idx = 0; idx < 4; idx++) {
            facc[idx] += __shfl_xor_sync(0xffffffffu, facc[idx], 1);
            facc[idx] += __shfl_xor_sync(0xffffffffu, facc[idx], 2);
            gacc[idx] += __shfl_xor_sync(0xffffffffu, gacc[idx], 1);
            gacc[idx] += __shfl_xor_sync(0xffffffffu, gacc[idx], 2);
        }
        if (q == 0) {
            #pragma unroll
            for (int mt = 0; mt < 2; mt++) {
                #pragma unroll
                for (int s = 0; s < 2; s++) {
                    int row = row0 + wm * 32 + mt * 16 + g + s * 8;
                    long w = (long)b * NN + row;
                    atomicAdd(&fOut[w], facc[mt * 2 + s]);
                    atomicAdd(&gOut[w], gacc[mt * 2 + s]);
                }
            }
        }
    }
}

// ---------------- sparse softmax over neighbor lists ----------------
__global__ void softmax_sparse_kernel(const float* __restrict__ f, const float* __restrict__ g,
                                      const int* __restrict__ nnz, const int* __restrict__ cols,
                                      float* __restrict__ Pc, int totalRows) {
    int w = (int)(((long)blockIdx.x * blockDim.x + threadIdx.x) >> 5);
    int lane = threadIdx.x & 31;
    if (w >= totalRows) return;
    int b = w >> 9;
    int i = w & 511;
    float fi = f[w];
    const float* gb = g + (long)b * NN;
    int n = nnz[i];
    const int* crow = cols + i * MAXN;
    int nc = (n + 31) >> 5;

    float e[4];
    float mx = -INFINITY;
    for (int c = 0; c < nc; c++) {
        int k = c * 32 + lane;
        float v = -INFINITY;
        if (k < n) {
            float xv = fi + gb[crow[k]];
            v = (xv >= 0.f) ? xv : 0.2f * xv;
        }
        e[c] = v;
        mx = fmaxf(mx, v);
    }
    #pragma unroll
    for (int o = 16; o > 0; o >>= 1) mx = fmaxf(mx, __shfl_xor_sync(0xffffffffu, mx, o));

    float s = 0.f;
    for (int c = 0; c < nc; c++) {
        float ev = (e[c] > -1e30f) ? __expf(e[c] - mx) : 0.f;
        e[c] = ev; s += ev;
    }
    #pragma unroll
    for (int o = 16; o > 0; o >>= 1) s += __shfl_xor_sync(0xffffffffu, s, o);
    float inv = 1.0f / s;

    float* prow = Pc + (long)w * MAXN;
    for (int c = 0; c < nc; c++) {
        int k = c * 32 + lane;
        if (k < n) prow[k] = e[c] * inv;
    }
}

// ---------------- sparse attention apply; 32-col chunks (3 blocks/SM) ----------------
__global__ __launch_bounds__(256)
void spmm_kernel(const float* __restrict__ Pc, const float* __restrict__ Wh,
                 const int* __restrict__ nnz, const int* __restrict__ cols,
                 __half* __restrict__ Chi, __half* __restrict__ Clo,
                 float* __restrict__ Cf, int writeF,
                 long whStride, long cOuter, int cDiv, long cInner, int ldc, int epi) {
    extern __shared__ float WhS[];     // [NN][SCH]
    int b = blockIdx.y;
    int c0 = blockIdx.x * SCH;
    const float* Whb = Wh + (long)b * whStride;
    long cOff = (long)(b / cDiv) * cOuter + (long)(b % cDiv) * cInner;

    for (int idx = threadIdx.x; idx < NN * (SCH / 4); idx += 256) {
        int row = idx >> 3;
        int col4 = (idx & 7) << 2;
        *(float4*)&WhS[row * SCH + col4] =
            *(const float4*)&Whb[(long)row * FF + c0 + col4];
    }
    __syncthreads();

    int warp = threadIdx.x >> 5;
    int lane = threadIdx.x & 31;
    for (int i = warp; i < NN; i += 8) {
        int n = nnz[i];
        const int* crow = cols + i * MAXN;
        const float* prow = Pc + ((long)b * NN + i) * MAXN;
        float a0 = 0.f;
        #pragma unroll 4
        for (int k = 0; k < n; k++) {
            int j = crow[k];
            float wv = prow[k];
            a0 += wv * WhS[j * SCH + lane];
        }
        if (epi >= 1) a0 = (a0 >= 0.f) ? a0 : expm1f(a0);
        if (epi == 2) a0 = (a0 >= 0.f) ? a0 : expm1f(a0);
        long o = cOff + (long)i * ldc + c0 + lane;
        __half h, l; split_h(a0, h, l);
        Chi[o] = h; Clo[o] = l;
        if (writeF) Cf[o] = a0;
    }
}

// ---------------- final pool ----------------
__global__ void pool_kernel(const float* __restrict__ x, const float* __restrict__ Wo,
                            const float* __restrict__ bo, float* __restrict__ out) {
    int t = blockIdx.x;
    int f = threadIdx.x;
    __shared__ float m[FF];
    const float* xt = x + (long)t * NN * FF;
    float s = 0.f;
    for (int n = 0; n < NN; n++) s += xt[n * FF + f];
    m[f] = s * (1.0f / NN);
    __syncthreads();
    float o = bo[f];
    for (int k = 0; k < FF; k++) o += m[k] * Wo[k * FF + f];
    out[t * FF + f] = o;
}

// ---------------- host orchestration ----------------
extern "C" void kernel_launch(void* const* d_in, const int* in_sizes, int n_in,
                              void* d_out, int out_size) {
    const float* pose    = (const float*)d_in[0];
    const int*   adj     = (const int*)  d_in[1];
    const float* Wp      = (const float*)d_in[2];
    const float* bp      = (const float*)d_in[3];
    const float* W_heads = (const float*)d_in[4];
    const float* a_heads = (const float*)d_in[5];
    const float* W_out   = (const float*)d_in[6];
    const float* a_out   = (const float*)d_in[7];
    const float* Wo      = (const float*)d_in[8];
    const float* bo      = (const float*)d_in[9];
    float* out = (float*)d_out;

    float *x, *Wh, *fb, *gb, *P;
    __half *xh, *xl, *xch, *xcl, *Wth, *Woth;
    int *nnz, *colsArr;
    cudaGetSymbolAddress((void**)&x,    g_x);
    cudaGetSymbolAddress((void**)&Wh,   g_Wh);
    cudaGetSymbolAddress((void**)&xh,   g_xh);
    cudaGetSymbolAddress((void**)&xl,   g_xl);
    cudaGetSymbolAddress((void**)&xch,  g_xch);
    cudaGetSymbolAddress((void**)&xcl,  g_xcl);
    cudaGetSymbolAddress((void**)&Wth,  g_Wth);
    cudaGetSymbolAddress((void**)&Woth, g_Woth);
    cudaGetSymbolAddress((void**)&fb,   g_f);
    cudaGetSymbolAddress((void**)&gb,   g_g);
    cudaGetSymbolAddress((void**)&P,    g_P);
    cudaGetSymbolAddress((void**)&nnz,  g_nnz);
    cudaGetSymbolAddress((void**)&colsArr, g_cols);

    static bool attrSet = false;
    if (!attrSet) {
        cudaFuncSetAttribute(spmm_kernel,
                             cudaFuncAttributeMaxDynamicSharedMemorySize, NN * SCH * 4);
        cudaFuncSetAttribute(gemm_tc,
                             cudaFuncAttributeMaxDynamicSharedMemorySize, GEMM_SMEM);
        attrSet = true;
    }

    adjlist_kernel<<<NN, 256>>>(adj, nnz, colsArr);

    {
        dim3 blk(32, 8);
        dim3 gh(FF / 32, FF / 32, LL * HH);
        wsplit_kernel<<<gh, blk>>>(W_heads, Wth, FF, FF);
        dim3 go(FF / 32, (HH * FF) / 32, LL);
        wsplit_kernel<<<go, blk>>>(W_out, Woth, HH * FF, FF);
    }

    {
        long total = (long)T_FR * NN * FF;
        input_proj_kernel<<<(unsigned)((total + 255) / 256), 256>>>(pose, Wp, bp, xh, xl);
    }

    int zgrid = (T_FR * HH * NN + 255) / 256;

    for (int l = 0; l < LL; l++) {
        const __half* Wlh = Wth  + (long)l * HH * FF * FF;
        const __half* Woh = Woth + (long)l * FF * HH * FF;
        const float* al  = a_heads + (long)l * HH * 2 * FF;
        const float* aol = a_out   + (long)l * 2 * FF;

        // 2a. Wh = x @ W_heads  (fused f/g epilogue)
        zero_fg_kernel<<<zgrid, 256>>>(fb, gb);
        {
            dim3 grid(FF / 128, NN / 128, T_FR * HH);
            gemm_tc<<<grid, 256, GEMM_SMEM>>>(xh, xl, Wlh, Wh,
                FF, FF, FF, FF,
                (long)NN * FF, HH,
                (long)FF * FF, HH,
                (long)NN * FF, 1, 0,
                0, fb, gb, al, HH, 1);
        }
        // 2c. sparse softmax -> compact P
        {
            int rows = T_FR * HH * NN;
            softmax_sparse_kernel<<<(rows * 32 + 255) / 256, 256>>>(fb, gb, nnz, colsArr, P, rows);
        }
        // 2d. xcat = elu(P @ Wh) -> fp16 hi/lo
        {
            dim3 grid(FF / SCH, T_FR * HH);
            spmm_kernel<<<grid, 256, NN * SCH * 4>>>(P, Wh, nnz, colsArr,
                xch, xcl, (float*)0, 0,
                (long)NN * FF,
                (long)NN * HH * FF, HH, FF, HH * FF, 1);
        }
        // 2e. Whout = xcat @ W_out  (fused f/g epilogue)
        zero_fg_kernel<<<zgrid, 256>>>(fb, gb);
        {
            dim3 grid(FF / 128, NN / 128, T_FR);
            gemm_tc<<<grid, 256, GEMM_SMEM>>>(xch, xcl, Woh, Wh,
                HH * FF, HH * FF, HH * FF, FF,
                (long)NN * HH * FF, 1,
                0, 1,
                (long)NN * FF, 1, 0,
                0, fb, gb, aol, 1, 1);
        }
        // 2g. sparse softmax -> compact P
        {
            int rows = T_FR * NN;
            softmax_sparse_kernel<<<(rows * 32 + 255) / 256, 256>>>(fb, gb, nnz, colsArr, P, rows);
        }
        // 2h. x = elu(elu(P @ Whout)) -> fp16 hi/lo (+ fp32 last layer for pool)
        {
            dim3 grid(FF / SCH, T_FR);
            spmm_kernel<<<grid, 256, NN * SCH * 4>>>(P, Wh, nnz, colsArr,
                xh, xl, x, (l == LL - 1) ? 1 : 0,
                (long)NN * FF,
                (long)NN * FF, 1, 0, FF, 2);
        }
    }

    pool_kernel<<<T_FR, 256>>>(x, Wo, bo, out);
}